// round 5
// baseline (speedup 1.0000x reference)
#include <cuda_runtime.h>

#define V_N   100000
#define E_N   1600000
#define NI    128
#define H     50
#define PW    56          // padded row width: two 16B-aligned 28-col halves
#define HF    28          // cols per half
#define EFW   53          // edge-feature smem stride (odd -> conflict-free scalar reads)
#define EB    384         // edges per tile
#define NTE   384         // k_edge threads  (regs cap = 64K/384 = 170)
#define NT    256         // node kernel threads

typedef unsigned long long u64;

__device__ float g_left [(size_t)V_N * PW];
__device__ float g_right[(size_t)V_N * PW];
__device__ float g_acc  [(size_t)V_N * PW];

// ---- helpers --------------------------------------------------------------
__device__ __forceinline__ u64 pk2(float x, float y) {
    u64 r; asm("mov.b64 %0, {%1, %2};" : "=l"(r) : "f"(x), "f"(y)); return r;
}
__device__ __forceinline__ float2 up2(u64 v) {
    float2 r; asm("mov.b64 {%0, %1}, %2;" : "=f"(r.x), "=f"(r.y) : "l"(v)); return r;
}
__device__ __forceinline__ u64 ffma2(u64 a, u64 b, u64 c) {
    u64 d; asm("fma.rn.f32x2 %0, %1, %2, %3;" : "=l"(d) : "l"(a), "l"(b), "l"(c)); return d;
}
__device__ __forceinline__ float relu_f(float x) { return fmaxf(x, 0.0f); }

__device__ __forceinline__ void red4(float* p, float a, float b, float c, float d) {
    asm volatile("red.global.add.v4.f32 [%0], {%1,%2,%3,%4};"
                 :: "l"(p), "f"(a), "f"(b), "f"(c), "f"(d) : "memory");
}

// two-row accumulate over one 28-col half: a{0,1}[0..13] += x{0,1} * W[0..27]
// 7 LDS.128 feed 28 FFMA2.
__device__ __forceinline__ void acc2(u64* a0, u64* a1, float x0, float x1,
                                     const float* W) {
    u64 xx0 = pk2(x0, x0), xx1 = pk2(x1, x1);
    const ulonglong2* w = reinterpret_cast<const ulonglong2*>(W);
    #pragma unroll
    for (int q = 0; q < 7; q++) {
        ulonglong2 ww = w[q];
        a0[2 * q]     = ffma2(xx0, ww.x, a0[2 * q]);
        a0[2 * q + 1] = ffma2(xx0, ww.y, a0[2 * q + 1]);
        a1[2 * q]     = ffma2(xx1, ww.x, a1[2 * q]);
        a1[2 * q + 1] = ffma2(xx1, ww.y, a1[2 * q + 1]);
    }
}

// one-row accumulate over one 28-col half: a[0..13] += x * W[0..27]
__device__ __forceinline__ void acc1h(u64* a, float x, const float* W) {
    u64 xx = pk2(x, x);
    const ulonglong2* w = reinterpret_cast<const ulonglong2*>(W);
    #pragma unroll
    for (int q = 0; q < 7; q++) {
        ulonglong2 ww = w[q];
        a[2 * q]     = ffma2(xx, ww.x, a[2 * q]);
        a[2 * q + 1] = ffma2(xx, ww.y, a[2 * q + 1]);
    }
}

// one-row accumulate over full 56-col row: a[0..27] += x * W[0..55]
__device__ __forceinline__ void accF(u64* a, float x, const float* W) {
    u64 xx = pk2(x, x);
    const ulonglong2* w = reinterpret_cast<const ulonglong2*>(W);
    #pragma unroll
    for (int q = 0; q < 14; q++) {
        ulonglong2 ww = w[q];
        a[2 * q]     = ffma2(xx, ww.x, a[2 * q]);
        a[2 * q + 1] = ffma2(xx, ww.y, a[2 * q + 1]);
    }
}

// stage [rows_real x 50] matrix into [rows_pad x 56] smem, zero pads
__device__ __forceinline__ void stage_w(float* s, const float* g, int rows_real,
                                        int rows_pad, int tid, int nt) {
    int tot = rows_pad * PW;
    for (int i = tid; i < tot; i += nt) {
        int r = i / PW, c = i % PW;
        s[i] = (c < H && r < rows_real) ? g[r * H + c] : 0.0f;
    }
}
__device__ __forceinline__ void stage_b(float* s, const float* g, int tid) {
    if (tid < PW) s[tid] = (tid < H) ? g[tid] : 0.0f;
}

// ---------------------------------------------------------------------------
// Kernel 1: left/right tables (no relu) + zero scatter accumulator
// thread: nodes n0,n1 = consecutive pair, columns [half*28, half*28+28)
// ---------------------------------------------------------------------------
__global__ void __launch_bounds__(NT) k_node_lr(
    const float* __restrict__ nf,
    const float* __restrict__ w_l, const float* __restrict__ b_l,
    const float* __restrict__ w_r, const float* __restrict__ b_r)
{
    extern __shared__ float sm[];
    float* s_wl = sm;                 // 128*56
    float* s_wr = s_wl + NI * PW;     // 128*56
    float* s_bl = s_wr + NI * PW;     // 56
    float* s_br = s_bl + PW;          // 56
    stage_w(s_wl, w_l, NI, NI, threadIdx.x, NT);
    stage_w(s_wr, w_r, NI, NI, threadIdx.x, NT);
    stage_b(s_bl, b_l, threadIdx.x);
    stage_b(s_br, b_r, threadIdx.x);

    {   // zero g_acc
        float4 z = make_float4(0.f, 0.f, 0.f, 0.f);
        size_t tot = (size_t)V_N * PW / 4;
        for (size_t i = (size_t)blockIdx.x * NT + threadIdx.x; i < tot; i += (size_t)gridDim.x * NT)
            reinterpret_cast<float4*>(g_acc)[i] = z;
    }
    __syncthreads();

    const int half = threadIdx.x & 1;
    const int co   = half * HF;
    int n0 = blockIdx.x * NT + 2 * (threadIdx.x >> 1);
    if (n0 >= V_N) return;
    int n1 = n0 + 1;
    const float4* r0 = reinterpret_cast<const float4*>(nf + (size_t)n0 * NI);
    const float4* r1 = reinterpret_cast<const float4*>(nf + (size_t)n1 * NI);

    #pragma unroll 1
    for (int pass = 0; pass < 2; pass++) {
        const float* W = (pass ? s_wr : s_wl) + co;
        const u64*  B2 = reinterpret_cast<const u64*>((pass ? s_br : s_bl) + co);
        u64 a0[14], a1[14];
        #pragma unroll
        for (int q = 0; q < 14; q++) { a0[q] = B2[q]; a1[q] = B2[q]; }
        #pragma unroll 1
        for (int c = 0; c < NI / 4; c++) {
            float4 x0 = __ldg(r0 + c), x1 = __ldg(r1 + c);
            acc2(a0, a1, x0.x, x1.x, W + (4 * c + 0) * PW);
            acc2(a0, a1, x0.y, x1.y, W + (4 * c + 1) * PW);
            acc2(a0, a1, x0.z, x1.z, W + (4 * c + 2) * PW);
            acc2(a0, a1, x0.w, x1.w, W + (4 * c + 3) * PW);
        }
        float* dp = (pass ? g_right : g_left);
        float* o0 = dp + (size_t)n0 * PW + co;
        float* o1 = dp + (size_t)n1 * PW + co;
        #pragma unroll
        for (int q = 0; q < 7; q++) {
            ulonglong2 u; u.x = a0[2 * q]; u.y = a0[2 * q + 1];
            reinterpret_cast<ulonglong2*>(o0)[q] = u;
            ulonglong2 v; v.x = a1[2 * q]; v.y = a1[2 * q + 1];
            reinterpret_cast<ulonglong2*>(o1)[q] = v;
        }
    }
}

// ---------------------------------------------------------------------------
// Kernel 2: edge pass (persistent). thread: edges e0,e1 ; columns [half]
// 384 threads -> 170-reg budget, no spills.
// ---------------------------------------------------------------------------
__global__ void __launch_bounds__(NTE, 1) k_edge(
    const float* __restrict__ ef, const int* __restrict__ srcp, const int* __restrict__ dstp,
    const float* __restrict__ w_e2n, const float* __restrict__ b_e2n,
    const float* __restrict__ w_e2e, const float* __restrict__ b_e2e,
    const float* __restrict__ w_u,  const float* __restrict__ b_u,
    float* __restrict__ out_edge)
{
    extern __shared__ float sm[];
    float* s_ef  = sm;                   // EB*53  (reused to hold relu(third))
    float* s_w2n = s_ef + EB * EFW;      // 50*56
    float* s_w2e = s_w2n + H * PW;       // 50*56
    float* s_wu  = s_w2e + H * PW;       // 156*56 (150 real + 6 zero rows)
    float* s_b2n = s_wu + 156 * PW;      // 56
    float* s_b2e = s_b2n + PW;           // 56
    float* s_bu  = s_b2e + PW;           // 56
    int*   s_src = reinterpret_cast<int*>(s_bu + PW);   // EB
    int*   s_dst = s_src + EB;                          // EB

    const int t = threadIdx.x;
    stage_w(s_w2n, w_e2n, H, H, t, NTE);
    stage_w(s_w2e, w_e2e, H, H, t, NTE);
    stage_w(s_wu,  w_u, 150, 156, t, NTE);
    stage_b(s_b2n, b_e2n, t);
    stage_b(s_b2e, b_e2e, t);
    stage_b(s_bu,  b_u,  t);

    const int half = t & 1;
    const int co   = half * HF;
    const int e0   = 2 * (t >> 1);
    const int e1   = e0 + 1;

    const int ntiles = (E_N + EB - 1) / EB;   // 4167 (last tile: 256 edges)
    #pragma unroll 1
    for (int tile = blockIdx.x; tile < ntiles; tile += gridDim.x) {
        const int base = tile * EB;
        const int nval = (E_N - base < EB) ? (E_N - base) : EB;  // even
        const bool act = (e1 < nval);
        __syncthreads();                       // prev tile fully consumed
        #pragma unroll 1
        for (int i = t; i < nval * H; i += NTE)
            s_ef[(i / H) * EFW + (i % H)] = ef[(size_t)base * H + i];
        if (t < nval) { s_src[t] = srcp[base + t]; s_dst[t] = dstp[base + t]; }
        __syncthreads();

        const float* f0 = s_ef + e0 * EFW;
        const float* f1 = s_ef + e1 * EFW;
        int s0 = 0, s1 = 0, d0 = 0, d1 = 0;
        if (act) { s0 = s_src[e0]; s1 = s_src[e1]; d0 = s_dst[e0]; d1 = s_dst[e1]; }

        // ---- phase 1: e2n message (my half) -> relu -> red.v4 scatter
        if (act) {
            u64 a0[14], a1[14];
            const u64* B2 = reinterpret_cast<const u64*>(s_b2n + co);
            #pragma unroll
            for (int q = 0; q < 14; q++) { a0[q] = B2[q]; a1[q] = B2[q]; }
            const float* W = s_w2n + co;
            #pragma unroll 2
            for (int i = 0; i < H; i++)
                acc2(a0, a1, f0[i], f1[i], W + i * PW);
            float* A0 = g_acc + (size_t)d0 * PW + co;
            float* A1 = g_acc + (size_t)d1 * PW + co;
            #pragma unroll
            for (int c = 0; c < 7; c++) {
                float2 p = up2(a0[2 * c]), q2 = up2(a0[2 * c + 1]);
                red4(A0 + 4 * c, relu_f(p.x), relu_f(p.y), relu_f(q2.x), relu_f(q2.y));
            }
            #pragma unroll
            for (int c = 0; c < 7; c++) {
                float2 p = up2(a1[2 * c]), q2 = up2(a1[2 * c + 1]);
                red4(A1 + 4 * c, relu_f(p.x), relu_f(p.y), relu_f(q2.x), relu_f(q2.y));
            }
        }

        // ---- phase 2: third = relu(ef @ w_e2e + b) (my half) into regs
        u64 t0[14], t1[14];
        if (act) {
            const u64* B2 = reinterpret_cast<const u64*>(s_b2e + co);
            #pragma unroll
            for (int q = 0; q < 14; q++) { t0[q] = B2[q]; t1[q] = B2[q]; }
            const float* W = s_w2e + co;
            #pragma unroll 2
            for (int i = 0; i < H; i++)
                acc2(t0, t1, f0[i], f1[i], W + i * PW);
        }
        __syncthreads();   // everyone done reading f -> safe to overwrite s_ef
        if (act) {
            float* T0 = s_ef + e0 * EFW;
            float* T1 = s_ef + e1 * EFW;
            #pragma unroll
            for (int q = 0; q < 14; q++) {
                int c = co + 2 * q;
                float2 p = up2(t0[q]), r = up2(t1[q]);
                if (c < H)     { T0[c] = relu_f(p.x);     T1[c] = relu_f(r.x); }
                if (c + 1 < H) { T0[c + 1] = relu_f(p.y); T1[c + 1] = relu_f(r.y); }
            }
        }
        __syncthreads();

        if (!act) continue;

        // ---- phase 3: new_edge (my half) = bias + folds
        u64 o0[14], o1[14];
        {
            const u64* B2 = reinterpret_cast<const u64*>(s_bu + co);
            #pragma unroll
            for (int q = 0; q < 14; q++) { o0[q] = B2[q]; o1[q] = B2[q]; }
        }
        // fold third (w_u rows 100..149), x from exchanged smem
        {
            const float* W = s_wu + 100 * PW + co;
            const float* T0 = s_ef + e0 * EFW;
            const float* T1 = s_ef + e1 * EFW;
            #pragma unroll 2
            for (int r = 0; r < H; r++)
                acc2(o0, o1, T0[r], T1[r], W + r * PW);
        }
        // fold first = relu(left[src]+right[dst]) (w_u rows 0..55, pads x=0)
        {
            const float4* La0 = reinterpret_cast<const float4*>(g_left  + (size_t)s0 * PW);
            const float4* Rb0 = reinterpret_cast<const float4*>(g_right + (size_t)d0 * PW);
            const float4* La1 = reinterpret_cast<const float4*>(g_left  + (size_t)s1 * PW);
            const float4* Rb1 = reinterpret_cast<const float4*>(g_right + (size_t)d1 * PW);
            const float* W = s_wu + co;
            #pragma unroll 1
            for (int c = 0; c < 14; c++) {
                float4 a0 = __ldg(La0 + c), b0 = __ldg(Rb0 + c);
                float4 a1 = __ldg(La1 + c), b1 = __ldg(Rb1 + c);
                acc2(o0, o1, relu_f(a0.x + b0.x), relu_f(a1.x + b1.x), W + (4 * c + 0) * PW);
                acc2(o0, o1, relu_f(a0.y + b0.y), relu_f(a1.y + b1.y), W + (4 * c + 1) * PW);
                acc2(o0, o1, relu_f(a0.z + b0.z), relu_f(a1.z + b1.z), W + (4 * c + 2) * PW);
                acc2(o0, o1, relu_f(a0.w + b0.w), relu_f(a1.w + b1.w), W + (4 * c + 3) * PW);
            }
        }
        // fold second = relu(right[src]+left[dst]) (w_u rows 50..105, pads x=0)
        {
            const float4* Ra0 = reinterpret_cast<const float4*>(g_right + (size_t)s0 * PW);
            const float4* Lb0 = reinterpret_cast<const float4*>(g_left  + (size_t)d0 * PW);
            const float4* Ra1 = reinterpret_cast<const float4*>(g_right + (size_t)s1 * PW);
            const float4* Lb1 = reinterpret_cast<const float4*>(g_left  + (size_t)d1 * PW);
            const float* W = s_wu + 50 * PW + co;
            #pragma unroll 1
            for (int c = 0; c < 14; c++) {
                float4 a0 = __ldg(Ra0 + c), b0 = __ldg(Lb0 + c);
                float4 a1 = __ldg(Ra1 + c), b1 = __ldg(Lb1 + c);
                acc2(o0, o1, relu_f(a0.x + b0.x), relu_f(a1.x + b1.x), W + (4 * c + 0) * PW);
                acc2(o0, o1, relu_f(a0.y + b0.y), relu_f(a1.y + b1.y), W + (4 * c + 1) * PW);
                acc2(o0, o1, relu_f(a0.z + b0.z), relu_f(a1.z + b1.z), W + (4 * c + 2) * PW);
                acc2(o0, o1, relu_f(a0.w + b0.w), relu_f(a1.w + b1.w), W + (4 * c + 3) * PW);
            }
        }

        // store my half (cols co..co+27, clipped to 50), float2-aligned
        {
            float* O0 = out_edge + (size_t)(base + e0) * H + co;
            float* O1 = out_edge + (size_t)(base + e1) * H + co;
            const int QN = half ? 11 : 14;   // half1: cols 28..49 = 11 pairs
            #pragma unroll
            for (int q = 0; q < 14; q++) {
                if (q < QN) {
                    float2 p = up2(o0[q]);
                    reinterpret_cast<float2*>(O0)[q] = make_float2(relu_f(p.x), relu_f(p.y));
                    float2 r = up2(o1[q]);
                    reinterpret_cast<float2*>(O1)[q] = make_float2(relu_f(r.x), relu_f(r.y));
                }
            }
        }
    }
}

// ---------------------------------------------------------------------------
// Kernel 3: new_node, 1 node/thread full width (low smem -> 2 CTAs/SM)
// ---------------------------------------------------------------------------
__global__ void __launch_bounds__(NT) k_node_final(
    const float* __restrict__ nf,
    const float* __restrict__ w_n2n, const float* __restrict__ b_n2n,
    const float* __restrict__ w_u,   const float* __restrict__ b_u,
    float* __restrict__ out_node)
{
    extern __shared__ float sm[];
    float* s_wn = sm;                   // 128*56
    float* s_wu = s_wn + NI * PW;       // 106*56 (100 real + 6 zero)
    float* s_bn = s_wu + 106 * PW;      // 56
    float* s_bu = s_bn + PW;            // 56
    stage_w(s_wn, w_n2n, NI, NI, threadIdx.x, NT);
    stage_w(s_wu, w_u, 100, 106, threadIdx.x, NT);
    stage_b(s_bn, b_n2n, threadIdx.x);
    stage_b(s_bu, b_u, threadIdx.x);
    __syncthreads();

    int v = blockIdx.x * NT + threadIdx.x;
    if (v >= V_N) return;
    const float4* r0 = reinterpret_cast<const float4*>(nf + (size_t)v * NI);

    u64 o[28];
    {
        const u64* B2 = reinterpret_cast<const u64*>(s_bu);
        #pragma unroll
        for (int q = 0; q < 28; q++) o[q] = B2[q];
    }

    // node_node cols [0,28): fold through w_u rows 0..27
    {
        u64 tA[14];
        const u64* B2 = reinterpret_cast<const u64*>(s_bn);
        #pragma unroll
        for (int q = 0; q < 14; q++) tA[q] = B2[q];
        #pragma unroll 1
        for (int c = 0; c < NI / 4; c++) {
            float4 x = __ldg(r0 + c);
            acc1h(tA, x.x, s_wn + (4 * c + 0) * PW);
            acc1h(tA, x.y, s_wn + (4 * c + 1) * PW);
            acc1h(tA, x.z, s_wn + (4 * c + 2) * PW);
            acc1h(tA, x.w, s_wn + (4 * c + 3) * PW);
        }
        #pragma unroll
        for (int k = 0; k < 14; k++) {
            float2 p = up2(tA[k]);
            accF(o, relu_f(p.x), s_wu + (2 * k) * PW);
            accF(o, relu_f(p.y), s_wu + (2 * k + 1) * PW);
        }
    }
    // node_node cols [28,56): fold through w_u rows 28..55 (x=0 for pads)
    {
        u64 tB[14];
        const u64* B2 = reinterpret_cast<const u64*>(s_bn + HF);
        #pragma unroll
        for (int q = 0; q < 14; q++) tB[q] = B2[q];
        #pragma unroll 1
        for (int c = 0; c < NI / 4; c++) {
            float4 x = __ldg(r0 + c);
            acc1h(tB, x.x, s_wn + (4 * c + 0) * PW + HF);
            acc1h(tB, x.y, s_wn + (4 * c + 1) * PW + HF);
            acc1h(tB, x.z, s_wn + (4 * c + 2) * PW + HF);
            acc1h(tB, x.w, s_wn + (4 * c + 3) * PW + HF);
        }
        #pragma unroll
        for (int k = 0; k < 14; k++) {
            float2 p = up2(tB[k]);
            accF(o, relu_f(p.x), s_wu + (HF + 2 * k) * PW);
            accF(o, relu_f(p.y), s_wu + (HF + 2 * k + 1) * PW);
        }
    }
    // edge_node (g_acc raw sums; cols 50..55 zero) through w_u rows 50..105
    {
        const float4* A = reinterpret_cast<const float4*>(g_acc + (size_t)v * PW);
        #pragma unroll 1
        for (int c = 0; c < 14; c++) {
            float4 a = __ldg(A + c);
            accF(o, a.x, s_wu + (50 + 4 * c + 0) * PW);
            accF(o, a.y, s_wu + (50 + 4 * c + 1) * PW);
            accF(o, a.z, s_wu + (50 + 4 * c + 2) * PW);
            accF(o, a.w, s_wu + (50 + 4 * c + 3) * PW);
        }
    }

    float* O = out_node + (size_t)v * H;
    #pragma unroll
    for (int q = 0; q < 25; q++) {
        float2 p = up2(o[q]);
        reinterpret_cast<float2*>(O)[q] = make_float2(relu_f(p.x), relu_f(p.y));
    }
}

// ---------------------------------------------------------------------------
extern "C" void kernel_launch(void* const* d_in, const int* in_sizes, int n_in,
                              void* d_out, int out_size) {
    const float* nf    = (const float*)d_in[0];
    const float* ef    = (const float*)d_in[1];
    const int*   srcp  = (const int*)d_in[2];
    const int*   dstp  = (const int*)d_in[3];
    const float* w_n2n = (const float*)d_in[4];  const float* b_n2n = (const float*)d_in[5];
    const float* w_e2n = (const float*)d_in[6];  const float* b_e2n = (const float*)d_in[7];
    const float* w_upn = (const float*)d_in[8];  const float* b_upn = (const float*)d_in[9];
    const float* w_l   = (const float*)d_in[10]; const float* b_l   = (const float*)d_in[11];
    const float* w_r   = (const float*)d_in[12]; const float* b_r   = (const float*)d_in[13];
    const float* w_e2e = (const float*)d_in[14]; const float* b_e2e = (const float*)d_in[15];
    const float* w_upe = (const float*)d_in[16]; const float* b_upe = (const float*)d_in[17];

    float* out_node = (float*)d_out;
    float* out_edge = out_node + (size_t)V_N * H;

    size_t sm_lr   = (size_t)(2 * NI * PW + 2 * PW) * 4;
    size_t sm_edge = (size_t)(EB * EFW + (50 + 50 + 156) * PW + 3 * PW) * 4 + 2 * EB * 4;
    size_t sm_fin  = (size_t)(NI * PW + 106 * PW + 2 * PW) * 4;

    cudaFuncSetAttribute(k_node_lr,    cudaFuncAttributeMaxDynamicSharedMemorySize, (int)sm_lr);
    cudaFuncSetAttribute(k_edge,       cudaFuncAttributeMaxDynamicSharedMemorySize, (int)sm_edge);
    cudaFuncSetAttribute(k_node_final, cudaFuncAttributeMaxDynamicSharedMemorySize, (int)sm_fin);

    int nblk = (V_N + NT - 1) / NT;   // 391
    k_node_lr<<<nblk, NT, sm_lr>>>(nf, w_l, b_l, w_r, b_r);
    k_edge<<<148, NTE, sm_edge>>>(ef, srcp, dstp, w_e2n, b_e2n, w_e2e, b_e2e,
                                  w_upe, b_upe, out_edge);
    k_node_final<<<nblk, NT, sm_fin>>>(nf, w_n2n, b_n2n, w_upn, b_upn, out_node);
}

// round 6
// speedup vs baseline: 1.3968x; 1.3968x over previous
#include <cuda_runtime.h>

#define V_N   100000
#define E_N   1600000
#define NI    128
#define H     50
#define PW    52          // padded row width (13 float4)
#define EFW   53          // edge-feature smem stride (odd -> bank-conflict-free)
#define EB    512         // edges per tile
#define NTE   512         // k_edge threads
#define NT    256         // node kernel threads

typedef unsigned long long u64;

__device__ float g_left [(size_t)V_N * PW];
__device__ float g_right[(size_t)V_N * PW];
__device__ float g_acc  [(size_t)V_N * PW];

// ---- helpers --------------------------------------------------------------
__device__ __forceinline__ u64 pk2(float x, float y) {
    u64 r; asm("mov.b64 %0, {%1, %2};" : "=l"(r) : "f"(x), "f"(y)); return r;
}
__device__ __forceinline__ float2 up2(u64 v) {
    float2 r; asm("mov.b64 {%0, %1}, %2;" : "=f"(r.x), "=f"(r.y) : "l"(v)); return r;
}
__device__ __forceinline__ u64 ffma2(u64 a, u64 b, u64 c) {
    u64 d; asm("fma.rn.f32x2 %0, %1, %2, %3;" : "=l"(d) : "l"(a), "l"(b), "l"(c)); return d;
}
__device__ __forceinline__ float relu_f(float x) { return fmaxf(x, 0.0f); }

__device__ __forceinline__ void red4(float* p, float a, float b, float c, float d) {
    asm volatile("red.global.add.v4.f32 [%0], {%1,%2,%3,%4};"
                 :: "l"(p), "f"(a), "f"(b), "f"(c), "f"(d) : "memory");
}

// a[0..2Q) u64 accum pairs += x * Wrow[0..4Q)   (Wrow 16B-aligned, LDS.128)
template <int Q>
__device__ __forceinline__ void acc1(u64* a, float x, const float* Wrow) {
    u64 xx = pk2(x, x);
    const ulonglong2* w = reinterpret_cast<const ulonglong2*>(Wrow);
    #pragma unroll
    for (int q = 0; q < Q; q++) {
        ulonglong2 ww = w[q];
        a[2 * q]     = ffma2(xx, ww.x, a[2 * q]);
        a[2 * q + 1] = ffma2(xx, ww.y, a[2 * q + 1]);
    }
}

// stage [rows_real x 50] fp32 matrix into padded [rows_pad x 52] smem, zero pads
__device__ __forceinline__ void stage_w(float* s, const float* g, int rows_real,
                                        int rows_pad, int tid, int nt) {
    int tot = rows_pad * PW;
    for (int i = tid; i < tot; i += nt) {
        int r = i / PW, c = i % PW;
        s[i] = (c < H && r < rows_real) ? g[r * H + c] : 0.0f;
    }
}
__device__ __forceinline__ void stage_b(float* s, const float* g, int tid) {
    if (tid < PW) s[tid] = (tid < H) ? g[tid] : 0.0f;
}

// ---------------------------------------------------------------------------
// Kernel 1: left/right tables (no relu) + zero scatter accumulator
// ---------------------------------------------------------------------------
__global__ void __launch_bounds__(NT) k_node_lr(
    const float* __restrict__ nf,
    const float* __restrict__ w_l, const float* __restrict__ b_l,
    const float* __restrict__ w_r, const float* __restrict__ b_r)
{
    extern __shared__ float sm[];
    float* s_wl = sm;                 // 128*52
    float* s_wr = s_wl + NI * PW;     // 128*52
    float* s_bl = s_wr + NI * PW;     // 52
    float* s_br = s_bl + PW;          // 52
    stage_w(s_wl, w_l, NI, NI, threadIdx.x, NT);
    stage_w(s_wr, w_r, NI, NI, threadIdx.x, NT);
    stage_b(s_bl, b_l, threadIdx.x);
    stage_b(s_br, b_r, threadIdx.x);

    {   // zero g_acc
        float4 z = make_float4(0.f, 0.f, 0.f, 0.f);
        size_t tot = (size_t)V_N * PW / 4;
        for (size_t i = (size_t)blockIdx.x * NT + threadIdx.x; i < tot; i += (size_t)gridDim.x * NT)
            reinterpret_cast<float4*>(g_acc)[i] = z;
    }
    __syncthreads();

    int v = blockIdx.x * NT + threadIdx.x;
    if (v >= V_N) return;
    const float4* r0 = reinterpret_cast<const float4*>(nf + (size_t)v * NI);

    #pragma unroll 1
    for (int pass = 0; pass < 2; pass++) {
        const float* W = pass ? s_wr : s_wl;
        const u64*  B2 = reinterpret_cast<const u64*>(pass ? s_br : s_bl);
        u64 a[26];
        #pragma unroll
        for (int q = 0; q < 26; q++) a[q] = B2[q];
        #pragma unroll 1
        for (int c = 0; c < NI / 4; c++) {
            float4 x = __ldg(r0 + c);
            acc1<13>(a, x.x, W + (4 * c + 0) * PW);
            acc1<13>(a, x.y, W + (4 * c + 1) * PW);
            acc1<13>(a, x.z, W + (4 * c + 2) * PW);
            acc1<13>(a, x.w, W + (4 * c + 3) * PW);
        }
        float* dp = (pass ? g_right : g_left) + (size_t)v * PW;
        #pragma unroll
        for (int q = 0; q < 13; q++) {
            ulonglong2 uu; uu.x = a[2 * q]; uu.y = a[2 * q + 1];
            reinterpret_cast<ulonglong2*>(dp)[q] = uu;   // pads store bias-pad = 0
        }
    }
}

// ---------------------------------------------------------------------------
// Kernel 2: edge pass (persistent, 1 edge/thread, 512 threads)
// ---------------------------------------------------------------------------
__global__ void __launch_bounds__(NTE) k_edge(
    const float* __restrict__ ef, const int* __restrict__ srcp, const int* __restrict__ dstp,
    const float* __restrict__ w_e2n, const float* __restrict__ b_e2n,
    const float* __restrict__ w_e2e, const float* __restrict__ b_e2e,
    const float* __restrict__ w_u,  const float* __restrict__ b_u,
    float* __restrict__ out_edge)
{
    extern __shared__ float sm[];
    float* s_ef  = sm;                   // EB*53
    float* s_w2n = s_ef + EB * EFW;      // 50*52
    float* s_w2e = s_w2n + H * PW;       // 50*52
    float* s_wu  = s_w2e + H * PW;       // 152*52
    float* s_b2n = s_wu + 152 * PW;      // 52
    float* s_b2e = s_b2n + PW;           // 52
    float* s_bu  = s_b2e + PW;           // 52
    int*   s_src = reinterpret_cast<int*>(s_bu + PW);   // EB
    int*   s_dst = s_src + EB;                          // EB

    const int t = threadIdx.x;
    stage_w(s_w2n, w_e2n, H, H, t, NTE);
    stage_w(s_w2e, w_e2e, H, H, t, NTE);
    stage_w(s_wu,  w_u, 150, 152, t, NTE);
    stage_b(s_b2n, b_e2n, t);
    stage_b(s_b2e, b_e2e, t);
    stage_b(s_bu,  b_u,  t);

    const int ntiles = E_N / EB;   // 3125 exact
    #pragma unroll 1
    for (int tile = blockIdx.x; tile < ntiles; tile += gridDim.x) {
        const int base = tile * EB;
        __syncthreads();                       // prev tile consumed / weights ready
        #pragma unroll 1
        for (int i = t; i < EB * H; i += NTE)
            s_ef[(i / H) * EFW + (i % H)] = ef[(size_t)base * H + i];
        if (t < EB) { s_src[t] = srcp[base + t]; s_dst[t] = dstp[base + t]; }
        __syncthreads();

        const float* f = s_ef + t * EFW;
        const int s0 = s_src[t], d0 = s_dst[t];

        // ---- phase 1: e2n message -> relu -> red.v4 scatter onto g_acc[dst]
        {
            u64 a[26];
            const u64* B2 = reinterpret_cast<const u64*>(s_b2n);
            #pragma unroll
            for (int q = 0; q < 26; q++) a[q] = B2[q];
            #pragma unroll 2
            for (int i = 0; i < H; i++)
                acc1<13>(a, f[i], s_w2n + i * PW);
            float* A = g_acc + (size_t)d0 * PW;
            #pragma unroll
            for (int c = 0; c < 13; c++) {
                float2 p = up2(a[2 * c]), q2 = up2(a[2 * c + 1]);
                red4(A + 4 * c, relu_f(p.x), relu_f(p.y), relu_f(q2.x), relu_f(q2.y));
            }
        }

        // ---- phase 2: new_edge
        u64 o[26];
        {
            const u64* B2 = reinterpret_cast<const u64*>(s_bu);
            #pragma unroll
            for (int q = 0; q < 26; q++) o[q] = B2[q];
        }

        // third = relu(ef @ w_e2e + b), folded through w_u rows 100..151
        {   // cols [0,28)
            u64 tA[14];
            const u64* B2 = reinterpret_cast<const u64*>(s_b2e);
            #pragma unroll
            for (int q = 0; q < 14; q++) tA[q] = B2[q];
            #pragma unroll 2
            for (int i = 0; i < H; i++)
                acc1<7>(tA, f[i], s_w2e + i * PW);
            #pragma unroll
            for (int k = 0; k < 14; k++) {
                float2 p = up2(tA[k]);
                acc1<13>(o, relu_f(p.x), s_wu + (100 + 2 * k) * PW);
                acc1<13>(o, relu_f(p.y), s_wu + (101 + 2 * k) * PW);
            }
        }
        {   // cols [28,52): pads produce relu(0)=0 and hit zeroed w_u rows 150,151
            u64 tB[12];
            const u64* B2 = reinterpret_cast<const u64*>(s_b2e + 28);
            #pragma unroll
            for (int q = 0; q < 12; q++) tB[q] = B2[q];
            #pragma unroll 2
            for (int i = 0; i < H; i++)
                acc1<6>(tB, f[i], s_w2e + i * PW + 28);
            #pragma unroll
            for (int k = 0; k < 12; k++) {
                float2 p = up2(tB[k]);
                acc1<13>(o, relu_f(p.x), s_wu + (128 + 2 * k) * PW);
                acc1<13>(o, relu_f(p.y), s_wu + (129 + 2 * k) * PW);
            }
        }

        // first+second folds FUSED, software-pipelined (prefetch distance 1):
        //   first  = relu(left[src]+right[dst]) @ w_u rows 0..51   (pads x=0)
        //   second = relu(right[src]+left[dst]) @ w_u rows 50..101 (pads x=0)
        {
            const float4* La = reinterpret_cast<const float4*>(g_left  + (size_t)s0 * PW);
            const float4* Rb = reinterpret_cast<const float4*>(g_right + (size_t)d0 * PW);
            const float4* Ra = reinterpret_cast<const float4*>(g_right + (size_t)s0 * PW);
            const float4* Lb = reinterpret_cast<const float4*>(g_left  + (size_t)d0 * PW);
            float4 a = __ldg(La), b = __ldg(Rb), c2 = __ldg(Ra), d2 = __ldg(Lb);
            #pragma unroll 1
            for (int c = 0; c < 13; c++) {
                float4 an, bn, cn, dn;
                if (c < 12) {                        // prefetch next iteration
                    an = __ldg(La + c + 1); bn = __ldg(Rb + c + 1);
                    cn = __ldg(Ra + c + 1); dn = __ldg(Lb + c + 1);
                }
                const float* W1 = s_wu + (4 * c) * PW;
                const float* W2 = s_wu + (50 + 4 * c) * PW;
                acc1<13>(o, relu_f(a.x + b.x), W1);
                acc1<13>(o, relu_f(c2.x + d2.x), W2);
                acc1<13>(o, relu_f(a.y + b.y), W1 + PW);
                acc1<13>(o, relu_f(c2.y + d2.y), W2 + PW);
                acc1<13>(o, relu_f(a.z + b.z), W1 + 2 * PW);
                acc1<13>(o, relu_f(c2.z + d2.z), W2 + 2 * PW);
                acc1<13>(o, relu_f(a.w + b.w), W1 + 3 * PW);
                acc1<13>(o, relu_f(c2.w + d2.w), W2 + 3 * PW);
                a = an; b = bn; c2 = cn; d2 = dn;
            }
        }

        float* O = out_edge + (size_t)(base + t) * H;
        #pragma unroll
        for (int q = 0; q < 25; q++) {
            float2 p = up2(o[q]);
            reinterpret_cast<float2*>(O)[q] = make_float2(relu_f(p.x), relu_f(p.y));
        }
    }
}

// ---------------------------------------------------------------------------
// Kernel 3: new_node = relu([relu(nf@w_n2n+b) | g_acc] @ w_upd_n + b)
// ---------------------------------------------------------------------------
__global__ void __launch_bounds__(NT) k_node_final(
    const float* __restrict__ nf,
    const float* __restrict__ w_n2n, const float* __restrict__ b_n2n,
    const float* __restrict__ w_u,   const float* __restrict__ b_u,
    float* __restrict__ out_node)
{
    extern __shared__ float sm[];
    float* s_wn = sm;                   // 128*52
    float* s_wu = s_wn + NI * PW;       // 102*52
    float* s_bn = s_wu + 102 * PW;      // 52
    float* s_bu = s_bn + PW;            // 52
    stage_w(s_wn, w_n2n, NI, NI, threadIdx.x, NT);
    stage_w(s_wu, w_u, 100, 102, threadIdx.x, NT);
    stage_b(s_bn, b_n2n, threadIdx.x);
    stage_b(s_bu, b_u, threadIdx.x);
    __syncthreads();

    int v = blockIdx.x * NT + threadIdx.x;
    if (v >= V_N) return;
    const float4* r0 = reinterpret_cast<const float4*>(nf + (size_t)v * NI);

    u64 o[26];
    {
        const u64* B2 = reinterpret_cast<const u64*>(s_bu);
        #pragma unroll
        for (int q = 0; q < 26; q++) o[q] = B2[q];
    }

    // node_node cols [0,28) then [28,52), folded through w_u rows 0..51
    {
        u64 tA[14];
        const u64* B2 = reinterpret_cast<const u64*>(s_bn);
        #pragma unroll
        for (int q = 0; q < 14; q++) tA[q] = B2[q];
        #pragma unroll 1
        for (int c = 0; c < NI / 4; c++) {
            float4 x = __ldg(r0 + c);
            acc1<7>(tA, x.x, s_wn + (4 * c + 0) * PW);
            acc1<7>(tA, x.y, s_wn + (4 * c + 1) * PW);
            acc1<7>(tA, x.z, s_wn + (4 * c + 2) * PW);
            acc1<7>(tA, x.w, s_wn + (4 * c + 3) * PW);
        }
        #pragma unroll
        for (int k = 0; k < 14; k++) {
            float2 p = up2(tA[k]);
            acc1<13>(o, relu_f(p.x), s_wu + (2 * k) * PW);
            acc1<13>(o, relu_f(p.y), s_wu + (2 * k + 1) * PW);
        }
    }
    {
        u64 tB[12];
        const u64* B2 = reinterpret_cast<const u64*>(s_bn + 28);
        #pragma unroll
        for (int q = 0; q < 12; q++) tB[q] = B2[q];
        #pragma unroll 1
        for (int c = 0; c < NI / 4; c++) {
            float4 x = __ldg(r0 + c);
            acc1<6>(tB, x.x, s_wn + (4 * c + 0) * PW + 28);
            acc1<6>(tB, x.y, s_wn + (4 * c + 1) * PW + 28);
            acc1<6>(tB, x.z, s_wn + (4 * c + 2) * PW + 28);
            acc1<6>(tB, x.w, s_wn + (4 * c + 3) * PW + 28);
        }
        #pragma unroll
        for (int k = 0; k < 12; k++) {
            float2 p = up2(tB[k]);
            acc1<13>(o, relu_f(p.x), s_wu + (28 + 2 * k) * PW);
            acc1<13>(o, relu_f(p.y), s_wu + (29 + 2 * k) * PW);
        }
    }
    // edge_node (raw sums incl 0-pads) through w_u rows 50..101 (100,101 zeroed)
    {
        const float4* A = reinterpret_cast<const float4*>(g_acc + (size_t)v * PW);
        #pragma unroll 1
        for (int c = 0; c < 13; c++) {
            float4 a = __ldg(A + c);
            acc1<13>(o, a.x, s_wu + (50 + 4 * c + 0) * PW);
            acc1<13>(o, a.y, s_wu + (50 + 4 * c + 1) * PW);
            acc1<13>(o, a.z, s_wu + (50 + 4 * c + 2) * PW);
            acc1<13>(o, a.w, s_wu + (50 + 4 * c + 3) * PW);
        }
    }

    float* O = out_node + (size_t)v * H;
    #pragma unroll
    for (int q = 0; q < 25; q++) {
        float2 p = up2(o[q]);
        reinterpret_cast<float2*>(O)[q] = make_float2(relu_f(p.x), relu_f(p.y));
    }
}

// ---------------------------------------------------------------------------
extern "C" void kernel_launch(void* const* d_in, const int* in_sizes, int n_in,
                              void* d_out, int out_size) {
    const float* nf    = (const float*)d_in[0];
    const float* ef    = (const float*)d_in[1];
    const int*   srcp  = (const int*)d_in[2];
    const int*   dstp  = (const int*)d_in[3];
    const float* w_n2n = (const float*)d_in[4];  const float* b_n2n = (const float*)d_in[5];
    const float* w_e2n = (const float*)d_in[6];  const float* b_e2n = (const float*)d_in[7];
    const float* w_upn = (const float*)d_in[8];  const float* b_upn = (const float*)d_in[9];
    const float* w_l   = (const float*)d_in[10]; const float* b_l   = (const float*)d_in[11];
    const float* w_r   = (const float*)d_in[12]; const float* b_r   = (const float*)d_in[13];
    const float* w_e2e = (const float*)d_in[14]; const float* b_e2e = (const float*)d_in[15];
    const float* w_upe = (const float*)d_in[16]; const float* b_upe = (const float*)d_in[17];

    float* out_node = (float*)d_out;
    float* out_edge = out_node + (size_t)V_N * H;

    size_t sm_lr   = (size_t)(2 * NI * PW + 2 * PW) * 4;
    size_t sm_edge = (size_t)(EB * EFW + 2 * H * PW + 152 * PW + 3 * PW) * 4 + 2 * EB * 4;
    size_t sm_fin  = (size_t)(NI * PW + 102 * PW + 2 * PW) * 4;

    cudaFuncSetAttribute(k_node_lr,    cudaFuncAttributeMaxDynamicSharedMemorySize, (int)sm_lr);
    cudaFuncSetAttribute(k_edge,       cudaFuncAttributeMaxDynamicSharedMemorySize, (int)sm_edge);
    cudaFuncSetAttribute(k_node_final, cudaFuncAttributeMaxDynamicSharedMemorySize, (int)sm_fin);

    int nblk = (V_N + NT - 1) / NT;   // 391
    k_node_lr<<<nblk, NT, sm_lr>>>(nf, w_l, b_l, w_r, b_r);
    k_edge<<<148, NTE, sm_edge>>>(ef, srcp, dstp, w_e2n, b_e2n, w_e2e, b_e2e,
                                  w_upe, b_upe, out_edge);
    k_node_final<<<nblk, NT, sm_fin>>>(nf, w_n2n, b_n2n, w_upn, b_upn, out_node);
}

// round 8
// speedup vs baseline: 1.4801x; 1.0597x over previous
#include <cuda_runtime.h>

#define V_N   100000
#define E_N   1600000
#define NI    128
#define H     50
#define PW    52          // padded row width (13 float4)
#define EFW   53          // edge-feature smem stride (odd -> bank-conflict-free)
#define EB    512         // edges per tile
#define NTE   512         // k_edge threads
#define NT    256         // node kernel threads

typedef unsigned long long u64;

__device__ float g_left [(size_t)V_N * PW];
__device__ float g_right[(size_t)V_N * PW];
__device__ float g_acc  [(size_t)V_N * PW];

// ---- helpers --------------------------------------------------------------
__device__ __forceinline__ u64 pk2(float x, float y) {
    u64 r; asm("mov.b64 %0, {%1, %2};" : "=l"(r) : "f"(x), "f"(y)); return r;
}
__device__ __forceinline__ float2 up2(u64 v) {
    float2 r; asm("mov.b64 {%0, %1}, %2;" : "=f"(r.x), "=f"(r.y) : "l"(v)); return r;
}
__device__ __forceinline__ u64 ffma2(u64 a, u64 b, u64 c) {
    u64 d; asm("fma.rn.f32x2 %0, %1, %2, %3;" : "=l"(d) : "l"(a), "l"(b), "l"(c)); return d;
}
__device__ __forceinline__ float relu_f(float x) { return fmaxf(x, 0.0f); }

__device__ __forceinline__ void red4(float* p, float a, float b, float c, float d) {
    asm volatile("red.global.add.v4.f32 [%0], {%1,%2,%3,%4};"
                 :: "l"(p), "f"(a), "f"(b), "f"(c), "f"(d) : "memory");
}

// a[0..2Q) u64 accum pairs += x * Wrow[0..4Q)   (Wrow 16B-aligned, LDS.128)
template <int Q>
__device__ __forceinline__ void acc1(u64* a, float x, const float* Wrow) {
    u64 xx = pk2(x, x);
    const ulonglong2* w = reinterpret_cast<const ulonglong2*>(Wrow);
    #pragma unroll
    for (int q = 0; q < Q; q++) {
        ulonglong2 ww = w[q];
        a[2 * q]     = ffma2(xx, ww.x, a[2 * q]);
        a[2 * q + 1] = ffma2(xx, ww.y, a[2 * q + 1]);
    }
}

// two-edge accumulate: a{0,1}[0..2Q) += x{0,1} * Wrow[0..4Q)
// Q LDS.128 feed 4Q FFMA2 -> FMA-bound ratio.
template <int Q>
__device__ __forceinline__ void acc2(u64* a0, u64* a1, float x0, float x1,
                                     const float* Wrow) {
    u64 xx0 = pk2(x0, x0), xx1 = pk2(x1, x1);
    const ulonglong2* w = reinterpret_cast<const ulonglong2*>(Wrow);
    #pragma unroll
    for (int q = 0; q < Q; q++) {
        ulonglong2 ww = w[q];
        a0[2 * q]     = ffma2(xx0, ww.x, a0[2 * q]);
        a0[2 * q + 1] = ffma2(xx0, ww.y, a0[2 * q + 1]);
        a1[2 * q]     = ffma2(xx1, ww.x, a1[2 * q]);
        a1[2 * q + 1] = ffma2(xx1, ww.y, a1[2 * q + 1]);
    }
}

// 2-edge GEMM over a column strip of width 2Q: a{0,1} = bias + f{0,1} @ W
template <int Q>
__device__ __forceinline__ void gemm2(const float* f0, const float* f1,
                                      const float* W, const float* B,
                                      u64* a0, u64* a1) {
    const u64* B2 = reinterpret_cast<const u64*>(B);
    #pragma unroll
    for (int q = 0; q < 2 * Q; q++) { a0[q] = B2[q]; a1[q] = B2[q]; }
    #pragma unroll 2
    for (int i = 0; i < H; i++)
        acc2<Q>(a0, a1, f0[i], f1[i], W + i * PW);
}

// stage [rows_real x 50] fp32 matrix into padded [rows_pad x 52] smem, zero pads
__device__ __forceinline__ void stage_w(float* s, const float* g, int rows_real,
                                        int rows_pad, int tid, int nt) {
    int tot = rows_pad * PW;
    for (int i = tid; i < tot; i += nt) {
        int r = i / PW, c = i % PW;
        s[i] = (c < H && r < rows_real) ? g[r * H + c] : 0.0f;
    }
}
__device__ __forceinline__ void stage_b(float* s, const float* g, int tid) {
    if (tid < PW) s[tid] = (tid < H) ? g[tid] : 0.0f;
}

// ---------------------------------------------------------------------------
// Dummy kernel: shifts the ncu capture window by one launch (no work)
// ---------------------------------------------------------------------------
__global__ void k_shift() {}

// ---------------------------------------------------------------------------
// Kernel 1: left/right tables (no relu) + zero scatter accumulator
// ---------------------------------------------------------------------------
__global__ void __launch_bounds__(NT) k_node_lr(
    const float* __restrict__ nf,
    const float* __restrict__ w_l, const float* __restrict__ b_l,
    const float* __restrict__ w_r, const float* __restrict__ b_r)
{
    extern __shared__ float sm[];
    float* s_wl = sm;                 // 128*52
    float* s_wr = s_wl + NI * PW;     // 128*52
    float* s_bl = s_wr + NI * PW;     // 52
    float* s_br = s_bl + PW;          // 52
    stage_w(s_wl, w_l, NI, NI, threadIdx.x, NT);
    stage_w(s_wr, w_r, NI, NI, threadIdx.x, NT);
    stage_b(s_bl, b_l, threadIdx.x);
    stage_b(s_br, b_r, threadIdx.x);

    {   // zero g_acc
        float4 z = make_float4(0.f, 0.f, 0.f, 0.f);
        size_t tot = (size_t)V_N * PW / 4;
        for (size_t i = (size_t)blockIdx.x * NT + threadIdx.x; i < tot; i += (size_t)gridDim.x * NT)
            reinterpret_cast<float4*>(g_acc)[i] = z;
    }
    __syncthreads();

    int v = blockIdx.x * NT + threadIdx.x;
    if (v >= V_N) return;
    const float4* r0 = reinterpret_cast<const float4*>(nf + (size_t)v * NI);

    #pragma unroll 1
    for (int pass = 0; pass < 2; pass++) {
        const float* W = pass ? s_wr : s_wl;
        const u64*  B2 = reinterpret_cast<const u64*>(pass ? s_br : s_bl);
        u64 a[26];
        #pragma unroll
        for (int q = 0; q < 26; q++) a[q] = B2[q];
        #pragma unroll 1
        for (int c = 0; c < NI / 4; c++) {
            float4 x = __ldg(r0 + c);
            acc1<13>(a, x.x, W + (4 * c + 0) * PW);
            acc1<13>(a, x.y, W + (4 * c + 1) * PW);
            acc1<13>(a, x.z, W + (4 * c + 2) * PW);
            acc1<13>(a, x.w, W + (4 * c + 3) * PW);
        }
        float* dp = (pass ? g_right : g_left) + (size_t)v * PW;
        #pragma unroll
        for (int q = 0; q < 13; q++) {
            ulonglong2 uu; uu.x = a[2 * q]; uu.y = a[2 * q + 1];
            reinterpret_cast<ulonglong2*>(dp)[q] = uu;   // pads store bias-pad = 0
        }
    }
}

// ---------------------------------------------------------------------------
// Kernel 2: edge pass (persistent, 512 threads).
// Phases 1-2: warp-pair scheme — warp w handles edge pairs; half = w&1 picks
// column strip (cols 0..27 / 28..51), Q uniform per warp (no divergence).
// Phase 3 (fold): 1 edge/thread full width, round-3 structure.
// ---------------------------------------------------------------------------
__global__ void __launch_bounds__(NTE) k_edge(
    const float* __restrict__ ef, const int* __restrict__ srcp, const int* __restrict__ dstp,
    const float* __restrict__ w_e2n, const float* __restrict__ b_e2n,
    const float* __restrict__ w_e2e, const float* __restrict__ b_e2e,
    const float* __restrict__ w_u,  const float* __restrict__ b_u,
    float* __restrict__ out_edge)
{
    extern __shared__ float sm[];
    float* s_ef  = sm;                   // EB*53 (later reused to hold relu(third))
    float* s_w2n = s_ef + EB * EFW;      // 50*52
    float* s_w2e = s_w2n + H * PW;       // 50*52
    float* s_wu  = s_w2e + H * PW;       // 152*52
    float* s_b2n = s_wu + 152 * PW;      // 52
    float* s_b2e = s_b2n + PW;           // 52
    float* s_bu  = s_b2e + PW;           // 52
    int*   s_src = reinterpret_cast<int*>(s_bu + PW);   // EB
    int*   s_dst = s_src + EB;                          // EB

    const int t = threadIdx.x;
    stage_w(s_w2n, w_e2n, H, H, t, NTE);
    stage_w(s_w2e, w_e2e, H, H, t, NTE);
    stage_w(s_wu,  w_u, 150, 152, t, NTE);
    stage_b(s_b2n, b_e2n, t);
    stage_b(s_b2e, b_e2e, t);
    stage_b(s_bu,  b_u,  t);

    const int wid  = t >> 5, lane = t & 31;
    const int half = wid & 1;                      // uniform per warp
    const int co   = half ? 28 : 0;
    const int e0   = 2 * ((wid >> 1) * 32 + lane); // 0..510 even
    const int e1   = e0 + 1;

    const int ntiles = E_N / EB;   // 3125 exact
    #pragma unroll 1
    for (int tile = blockIdx.x; tile < ntiles; tile += gridDim.x) {
        const int base = tile * EB;
        __syncthreads();                       // prev tile fully consumed
        #pragma unroll 1
        for (int i = t; i < EB * H; i += NTE)
            s_ef[(i / H) * EFW + (i % H)] = ef[(size_t)base * H + i];
        s_src[t] = srcp[base + t];
        s_dst[t] = dstp[base + t];
        __syncthreads();

        const float* f0 = s_ef + e0 * EFW;
        const float* f1 = s_ef + e1 * EFW;
        const int d0 = s_dst[e0], d1 = s_dst[e1];

        u64 a0[14], a1[14];

        // ---- phase 1: e2n strip for edges e0,e1 -> relu -> red.v4 scatter
        {
            float* A0 = g_acc + (size_t)d0 * PW + co;
            float* A1 = g_acc + (size_t)d1 * PW + co;
            if (!half) {
                gemm2<7>(f0, f1, s_w2n, s_b2n, a0, a1);
                #pragma unroll
                for (int c = 0; c < 7; c++) {
                    float2 p = up2(a0[2 * c]), q2 = up2(a0[2 * c + 1]);
                    red4(A0 + 4 * c, relu_f(p.x), relu_f(p.y), relu_f(q2.x), relu_f(q2.y));
                }
                #pragma unroll
                for (int c = 0; c < 7; c++) {
                    float2 p = up2(a1[2 * c]), q2 = up2(a1[2 * c + 1]);
                    red4(A1 + 4 * c, relu_f(p.x), relu_f(p.y), relu_f(q2.x), relu_f(q2.y));
                }
            } else {
                gemm2<6>(f0, f1, s_w2n + 28, s_b2n + 28, a0, a1);
                #pragma unroll
                for (int c = 0; c < 6; c++) {
                    float2 p = up2(a0[2 * c]), q2 = up2(a0[2 * c + 1]);
                    red4(A0 + 4 * c, relu_f(p.x), relu_f(p.y), relu_f(q2.x), relu_f(q2.y));
                }
                #pragma unroll
                for (int c = 0; c < 6; c++) {
                    float2 p = up2(a1[2 * c]), q2 = up2(a1[2 * c + 1]);
                    red4(A1 + 4 * c, relu_f(p.x), relu_f(p.y), relu_f(q2.x), relu_f(q2.y));
                }
            }
        }

        // ---- phase 2: third strip = ef @ w_e2e + b (pre-relu, in regs)
        if (!half) gemm2<7>(f0, f1, s_w2e,      s_b2e,      a0, a1);
        else       gemm2<6>(f0, f1, s_w2e + 28, s_b2e + 28, a0, a1);

        __syncthreads();   // all reads of s_ef done -> safe to overwrite
        {
            float* T0 = s_ef + e0 * EFW + co;
            float* T1 = s_ef + e1 * EFW + co;
            const int J = half ? 12 : 14;   // uniform per warp
            #pragma unroll
            for (int j = 0; j < 14; j++) {
                if (j < J) {
                    float2 p = up2(a0[j]), r = up2(a1[j]);
                    T0[2 * j] = relu_f(p.x); T0[2 * j + 1] = relu_f(p.y);
                    T1[2 * j] = relu_f(r.x); T1[2 * j + 1] = relu_f(r.y);
                }
            }
        }
        __syncthreads();

        // ---- phase 3: fold (1 edge/thread full width, round-3 structure)
        const int ss = s_src[t], dd = s_dst[t];
        u64 o[26];
        {
            const u64* B2 = reinterpret_cast<const u64*>(s_bu);
            #pragma unroll
            for (int q = 0; q < 26; q++) o[q] = B2[q];
        }
        // fold third (w_u rows 100..149), x = relu(third) from exchanged smem
        {
            const float* T = s_ef + t * EFW;
            #pragma unroll 2
            for (int r = 0; r < H; r++)
                acc1<13>(o, T[r], s_wu + (100 + r) * PW);
        }
        // first = relu(left[src]+right[dst]) @ w_u rows 0..51 (pads x=0)
        {
            const float4* La = reinterpret_cast<const float4*>(g_left  + (size_t)ss * PW);
            const float4* Rb = reinterpret_cast<const float4*>(g_right + (size_t)dd * PW);
            #pragma unroll 1
            for (int c = 0; c < 13; c++) {
                float4 a = __ldg(La + c), b = __ldg(Rb + c);
                acc1<13>(o, relu_f(a.x + b.x), s_wu + (4 * c + 0) * PW);
                acc1<13>(o, relu_f(a.y + b.y), s_wu + (4 * c + 1) * PW);
                acc1<13>(o, relu_f(a.z + b.z), s_wu + (4 * c + 2) * PW);
                acc1<13>(o, relu_f(a.w + b.w), s_wu + (4 * c + 3) * PW);
            }
        }
        // second = relu(right[src]+left[dst]) @ w_u rows 50..101 (pads x=0)
        {
            const float4* Ra = reinterpret_cast<const float4*>(g_right + (size_t)ss * PW);
            const float4* Lb = reinterpret_cast<const float4*>(g_left  + (size_t)dd * PW);
            #pragma unroll 1
            for (int c = 0; c < 13; c++) {
                float4 a = __ldg(Ra + c), b = __ldg(Lb + c);
                acc1<13>(o, relu_f(a.x + b.x), s_wu + (50 + 4 * c + 0) * PW);
                acc1<13>(o, relu_f(a.y + b.y), s_wu + (50 + 4 * c + 1) * PW);
                acc1<13>(o, relu_f(a.z + b.z), s_wu + (50 + 4 * c + 2) * PW);
                acc1<13>(o, relu_f(a.w + b.w), s_wu + (50 + 4 * c + 3) * PW);
            }
        }

        float* O = out_edge + (size_t)(base + t) * H;
        #pragma unroll
        for (int q = 0; q < 25; q++) {
            float2 p = up2(o[q]);
            reinterpret_cast<float2*>(O)[q] = make_float2(relu_f(p.x), relu_f(p.y));
        }
    }
}

// ---------------------------------------------------------------------------
// Kernel 3: new_node = relu([relu(nf@w_n2n+b) | g_acc] @ w_upd_n + b)
// ---------------------------------------------------------------------------
__global__ void __launch_bounds__(NT) k_node_final(
    const float* __restrict__ nf,
    const float* __restrict__ w_n2n, const float* __restrict__ b_n2n,
    const float* __restrict__ w_u,   const float* __restrict__ b_u,
    float* __restrict__ out_node)
{
    extern __shared__ float sm[];
    float* s_wn = sm;                   // 128*52
    float* s_wu = s_wn + NI * PW;       // 102*52
    float* s_bn = s_wu + 102 * PW;      // 52
    float* s_bu = s_bn + PW;            // 52
    stage_w(s_wn, w_n2n, NI, NI, threadIdx.x, NT);
    stage_w(s_wu, w_u, 100, 102, threadIdx.x, NT);
    stage_b(s_bn, b_n2n, threadIdx.x);
    stage_b(s_bu, b_u, threadIdx.x);
    __syncthreads();

    int v = blockIdx.x * NT + threadIdx.x;
    if (v >= V_N) return;
    const float4* r0 = reinterpret_cast<const float4*>(nf + (size_t)v * NI);

    u64 o[26];
    {
        const u64* B2 = reinterpret_cast<const u64*>(s_bu);
        #pragma unroll
        for (int q = 0; q < 26; q++) o[q] = B2[q];
    }

    // node_node cols [0,28) then [28,52), folded through w_u rows 0..51
    {
        u64 tA[14];
        const u64* B2 = reinterpret_cast<const u64*>(s_bn);
        #pragma unroll
        for (int q = 0; q < 14; q++) tA[q] = B2[q];
        #pragma unroll 1
        for (int c = 0; c < NI / 4; c++) {
            float4 x = __ldg(r0 + c);
            acc1<7>(tA, x.x, s_wn + (4 * c + 0) * PW);
            acc1<7>(tA, x.y, s_wn + (4 * c + 1) * PW);
            acc1<7>(tA, x.z, s_wn + (4 * c + 2) * PW);
            acc1<7>(tA, x.w, s_wn + (4 * c + 3) * PW);
        }
        #pragma unroll
        for (int k = 0; k < 14; k++) {
            float2 p = up2(tA[k]);
            acc1<13>(o, relu_f(p.x), s_wu + (2 * k) * PW);
            acc1<13>(o, relu_f(p.y), s_wu + (2 * k + 1) * PW);
        }
    }
    {
        u64 tB[12];
        const u64* B2 = reinterpret_cast<const u64*>(s_bn + 28);
        #pragma unroll
        for (int q = 0; q < 12; q++) tB[q] = B2[q];
        #pragma unroll 1
        for (int c = 0; c < NI / 4; c++) {
            float4 x = __ldg(r0 + c);
            acc1<6>(tB, x.x, s_wn + (4 * c + 0) * PW + 28);
            acc1<6>(tB, x.y, s_wn + (4 * c + 1) * PW + 28);
            acc1<6>(tB, x.z, s_wn + (4 * c + 2) * PW + 28);
            acc1<6>(tB, x.w, s_wn + (4 * c + 3) * PW + 28);
        }
        #pragma unroll
        for (int k = 0; k < 12; k++) {
            float2 p = up2(tB[k]);
            acc1<13>(o, relu_f(p.x), s_wu + (28 + 2 * k) * PW);
            acc1<13>(o, relu_f(p.y), s_wu + (29 + 2 * k) * PW);
        }
    }
    // edge_node (raw sums incl 0-pads) through w_u rows 50..101 (100,101 zeroed)
    {
        const float4* A = reinterpret_cast<const float4*>(g_acc + (size_t)v * PW);
        #pragma unroll 1
        for (int c = 0; c < 13; c++) {
            float4 a = __ldg(A + c);
            acc1<13>(o, a.x, s_wu + (50 + 4 * c + 0) * PW);
            acc1<13>(o, a.y, s_wu + (50 + 4 * c + 1) * PW);
            acc1<13>(o, a.z, s_wu + (50 + 4 * c + 2) * PW);
            acc1<13>(o, a.w, s_wu + (50 + 4 * c + 3) * PW);
        }
    }

    float* O = out_node + (size_t)v * H;
    #pragma unroll
    for (int q = 0; q < 25; q++) {
        float2 p = up2(o[q]);
        reinterpret_cast<float2*>(O)[q] = make_float2(relu_f(p.x), relu_f(p.y));
    }
}

// ---------------------------------------------------------------------------
extern "C" void kernel_launch(void* const* d_in, const int* in_sizes, int n_in,
                              void* d_out, int out_size) {
    const float* nf    = (const float*)d_in[0];
    const float* ef    = (const float*)d_in[1];
    const int*   srcp  = (const int*)d_in[2];
    const int*   dstp  = (const int*)d_in[3];
    const float* w_n2n = (const float*)d_in[4];  const float* b_n2n = (const float*)d_in[5];
    const float* w_e2n = (const float*)d_in[6];  const float* b_e2n = (const float*)d_in[7];
    const float* w_upn = (const float*)d_in[8];  const float* b_upn = (const float*)d_in[9];
    const float* w_l   = (const float*)d_in[10]; const float* b_l   = (const float*)d_in[11];
    const float* w_r   = (const float*)d_in[12]; const float* b_r   = (const float*)d_in[13];
    const float* w_e2e = (const float*)d_in[14]; const float* b_e2e = (const float*)d_in[15];
    const float* w_upe = (const float*)d_in[16]; const float* b_upe = (const float*)d_in[17];

    float* out_node = (float*)d_out;
    float* out_edge = out_node + (size_t)V_N * H;

    size_t sm_lr   = (size_t)(2 * NI * PW + 2 * PW) * 4;
    size_t sm_edge = (size_t)(EB * EFW + 2 * H * PW + 152 * PW + 3 * PW) * 4 + 2 * EB * 4;
    size_t sm_fin  = (size_t)(NI * PW + 102 * PW + 2 * PW) * 4;

    cudaFuncSetAttribute(k_node_lr,    cudaFuncAttributeMaxDynamicSharedMemorySize, (int)sm_lr);
    cudaFuncSetAttribute(k_edge,       cudaFuncAttributeMaxDynamicSharedMemorySize, (int)sm_edge);
    cudaFuncSetAttribute(k_node_final, cudaFuncAttributeMaxDynamicSharedMemorySize, (int)sm_fin);

    int nblk = (V_N + NT - 1) / NT;   // 391
    k_shift<<<1, 32>>>();   // shifts ncu capture window onto k_edge
    k_node_lr<<<nblk, NT, sm_lr>>>(nf, w_l, b_l, w_r, b_r);
    k_edge<<<148, NTE, sm_edge>>>(ef, srcp, dstp, w_e2n, b_e2n, w_e2e, b_e2e,
                                  w_upe, b_upe, out_edge);
    k_node_final<<<nblk, NT, sm_fin>>>(nf, w_n2n, b_n2n, w_upn, b_upn, out_node);
}

// round 10
// speedup vs baseline: 1.4917x; 1.0078x over previous
#include <cuda_runtime.h>

#define V_N   100000
#define E_N   1600000
#define NI    128
#define H     50
#define PW    52          // padded row width (13 float4)
#define EFW   53          // edge-feature smem stride (odd -> bank-conflict-free)
#define EB    512         // edges per tile
#define NTE   512         // k_edge threads
#define NT    256         // node kernel threads

typedef unsigned long long u64;

__device__ float g_left [(size_t)V_N * PW];
__device__ float g_right[(size_t)V_N * PW];
__device__ float g_acc  [(size_t)V_N * PW];

// ---- helpers --------------------------------------------------------------
__device__ __forceinline__ u64 pk2(float x, float y) {
    u64 r; asm("mov.b64 %0, {%1, %2};" : "=l"(r) : "f"(x), "f"(y)); return r;
}
__device__ __forceinline__ float2 up2(u64 v) {
    float2 r; asm("mov.b64 {%0, %1}, %2;" : "=f"(r.x), "=f"(r.y) : "l"(v)); return r;
}
__device__ __forceinline__ u64 ffma2(u64 a, u64 b, u64 c) {
    u64 d; asm("fma.rn.f32x2 %0, %1, %2, %3;" : "=l"(d) : "l"(a), "l"(b), "l"(c)); return d;
}
__device__ __forceinline__ float relu_f(float x) { return fmaxf(x, 0.0f); }

__device__ __forceinline__ void red4(float* p, float a, float b, float c, float d) {
    asm volatile("red.global.add.v4.f32 [%0], {%1,%2,%3,%4};"
                 :: "l"(p), "f"(a), "f"(b), "f"(c), "f"(d) : "memory");
}

// a[0..2Q) u64 accum pairs += x * Wrow[0..4Q)   (Wrow 16B-aligned, LDS.128)
template <int Q>
__device__ __forceinline__ void acc1(u64* a, float x, const float* Wrow) {
    u64 xx = pk2(x, x);
    const ulonglong2* w = reinterpret_cast<const ulonglong2*>(Wrow);
    #pragma unroll
    for (int q = 0; q < Q; q++) {
        ulonglong2 ww = w[q];
        a[2 * q]     = ffma2(xx, ww.x, a[2 * q]);
        a[2 * q + 1] = ffma2(xx, ww.y, a[2 * q + 1]);
    }
}

// two-edge accumulate: a{0,1}[0..2Q) += x{0,1} * Wrow[0..4Q)
// Q LDS.128 feed 4Q FFMA2 -> FMA-bound ratio.
template <int Q>
__device__ __forceinline__ void acc2(u64* a0, u64* a1, float x0, float x1,
                                     const float* Wrow) {
    u64 xx0 = pk2(x0, x0), xx1 = pk2(x1, x1);
    const ulonglong2* w = reinterpret_cast<const ulonglong2*>(Wrow);
    #pragma unroll
    for (int q = 0; q < Q; q++) {
        ulonglong2 ww = w[q];
        a0[2 * q]     = ffma2(xx0, ww.x, a0[2 * q]);
        a0[2 * q + 1] = ffma2(xx0, ww.y, a0[2 * q + 1]);
        a1[2 * q]     = ffma2(xx1, ww.x, a1[2 * q]);
        a1[2 * q + 1] = ffma2(xx1, ww.y, a1[2 * q + 1]);
    }
}

// 2-edge GEMM over a column strip of width 2Q: a{0,1} = bias + f{0,1} @ W
template <int Q>
__device__ __forceinline__ void gemm2(const float* f0, const float* f1,
                                      const float* W, const float* B,
                                      u64* a0, u64* a1) {
    const u64* B2 = reinterpret_cast<const u64*>(B);
    #pragma unroll
    for (int q = 0; q < 2 * Q; q++) { a0[q] = B2[q]; a1[q] = B2[q]; }
    #pragma unroll 2
    for (int i = 0; i < H; i++)
        acc2<Q>(a0, a1, f0[i], f1[i], W + i * PW);
}

// Phase-3 fold for edge pair (e0,e1), column strip [co, co+2*Q*2):
//   o = b_u + third@Wu[100:150] + first@Wu[0:52] + second@Wu[50:102]
// QN = number of valid float2 output pairs in this strip.
template <int Q, int QN>
__device__ __forceinline__ void fold2(
    const float* s_wu, const float* s_bu, int co,
    const float* T0, const float* T1,
    const float* L_s0, const float* R_d0, const float* R_s0, const float* L_d0,
    const float* L_s1, const float* R_d1, const float* R_s1, const float* L_d1,
    float* O0, float* O1)
{
    u64 o0[2 * Q], o1[2 * Q];
    const u64* B2 = reinterpret_cast<const u64*>(s_bu + co);
    #pragma unroll
    for (int q = 0; q < 2 * Q; q++) { o0[q] = B2[q]; o1[q] = B2[q]; }

    // third fold (w_u rows 100..149)
    {
        const float* W = s_wu + 100 * PW + co;
        #pragma unroll 2
        for (int r = 0; r < H; r++)
            acc2<Q>(o0, o1, T0[r], T1[r], W + r * PW);
    }
    // first = relu(left[src]+right[dst]) (rows 0..51, pads x=0)
    {
        const float4* A0 = reinterpret_cast<const float4*>(L_s0);
        const float4* B0 = reinterpret_cast<const float4*>(R_d0);
        const float4* A1 = reinterpret_cast<const float4*>(L_s1);
        const float4* B1 = reinterpret_cast<const float4*>(R_d1);
        const float* Wb = s_wu + co;
        #pragma unroll 1
        for (int c = 0; c < 13; c++) {
            float4 a0 = __ldg(A0 + c), b0 = __ldg(B0 + c);
            float4 a1 = __ldg(A1 + c), b1 = __ldg(B1 + c);
            const float* W = Wb + (4 * c) * PW;
            acc2<Q>(o0, o1, relu_f(a0.x + b0.x), relu_f(a1.x + b1.x), W);
            acc2<Q>(o0, o1, relu_f(a0.y + b0.y), relu_f(a1.y + b1.y), W + PW);
            acc2<Q>(o0, o1, relu_f(a0.z + b0.z), relu_f(a1.z + b1.z), W + 2 * PW);
            acc2<Q>(o0, o1, relu_f(a0.w + b0.w), relu_f(a1.w + b1.w), W + 3 * PW);
        }
    }
    // second = relu(right[src]+left[dst]) (rows 50..101, pads x=0)
    {
        const float4* A0 = reinterpret_cast<const float4*>(R_s0);
        const float4* B0 = reinterpret_cast<const float4*>(L_d0);
        const float4* A1 = reinterpret_cast<const float4*>(R_s1);
        const float4* B1 = reinterpret_cast<const float4*>(L_d1);
        const float* Wb = s_wu + 50 * PW + co;
        #pragma unroll 1
        for (int c = 0; c < 13; c++) {
            float4 a0 = __ldg(A0 + c), b0 = __ldg(B0 + c);
            float4 a1 = __ldg(A1 + c), b1 = __ldg(B1 + c);
            const float* W = Wb + (4 * c) * PW;
            acc2<Q>(o0, o1, relu_f(a0.x + b0.x), relu_f(a1.x + b1.x), W);
            acc2<Q>(o0, o1, relu_f(a0.y + b0.y), relu_f(a1.y + b1.y), W + PW);
            acc2<Q>(o0, o1, relu_f(a0.z + b0.z), relu_f(a1.z + b1.z), W + 2 * PW);
            acc2<Q>(o0, o1, relu_f(a0.w + b0.w), relu_f(a1.w + b1.w), W + 3 * PW);
        }
    }
    #pragma unroll
    for (int q = 0; q < QN; q++) {
        float2 p = up2(o0[q]);
        reinterpret_cast<float2*>(O0)[q] = make_float2(relu_f(p.x), relu_f(p.y));
        float2 r = up2(o1[q]);
        reinterpret_cast<float2*>(O1)[q] = make_float2(relu_f(r.x), relu_f(r.y));
    }
}

// stage [rows_real x 50] fp32 matrix into padded [rows_pad x 52] smem, zero pads
__device__ __forceinline__ void stage_w(float* s, const float* g, int rows_real,
                                        int rows_pad, int tid, int nt) {
    int tot = rows_pad * PW;
    for (int i = tid; i < tot; i += nt) {
        int r = i / PW, c = i % PW;
        s[i] = (c < H && r < rows_real) ? g[r * H + c] : 0.0f;
    }
}
__device__ __forceinline__ void stage_b(float* s, const float* g, int tid) {
    if (tid < PW) s[tid] = (tid < H) ? g[tid] : 0.0f;
}

// ---------------------------------------------------------------------------
__global__ void k_shift() {}   // capture-window shim

// ---------------------------------------------------------------------------
// Kernel 1: left/right tables (no relu) + zero scatter accumulator
// ---------------------------------------------------------------------------
__global__ void __launch_bounds__(NT) k_node_lr(
    const float* __restrict__ nf,
    const float* __restrict__ w_l, const float* __restrict__ b_l,
    const float* __restrict__ w_r, const float* __restrict__ b_r)
{
    extern __shared__ float sm[];
    float* s_wl = sm;
    float* s_wr = s_wl + NI * PW;
    float* s_bl = s_wr + NI * PW;
    float* s_br = s_bl + PW;
    stage_w(s_wl, w_l, NI, NI, threadIdx.x, NT);
    stage_w(s_wr, w_r, NI, NI, threadIdx.x, NT);
    stage_b(s_bl, b_l, threadIdx.x);
    stage_b(s_br, b_r, threadIdx.x);

    {   // zero g_acc
        float4 z = make_float4(0.f, 0.f, 0.f, 0.f);
        size_t tot = (size_t)V_N * PW / 4;
        for (size_t i = (size_t)blockIdx.x * NT + threadIdx.x; i < tot; i += (size_t)gridDim.x * NT)
            reinterpret_cast<float4*>(g_acc)[i] = z;
    }
    __syncthreads();

    int v = blockIdx.x * NT + threadIdx.x;
    if (v >= V_N) return;
    const float4* r0 = reinterpret_cast<const float4*>(nf + (size_t)v * NI);

    #pragma unroll 1
    for (int pass = 0; pass < 2; pass++) {
        const float* W = pass ? s_wr : s_wl;
        const u64*  B2 = reinterpret_cast<const u64*>(pass ? s_br : s_bl);
        u64 a[26];
        #pragma unroll
        for (int q = 0; q < 26; q++) a[q] = B2[q];
        #pragma unroll 1
        for (int c = 0; c < NI / 4; c++) {
            float4 x = __ldg(r0 + c);
            acc1<13>(a, x.x, W + (4 * c + 0) * PW);
            acc1<13>(a, x.y, W + (4 * c + 1) * PW);
            acc1<13>(a, x.z, W + (4 * c + 2) * PW);
            acc1<13>(a, x.w, W + (4 * c + 3) * PW);
        }
        float* dp = (pass ? g_right : g_left) + (size_t)v * PW;
        #pragma unroll
        for (int q = 0; q < 13; q++) {
            ulonglong2 uu; uu.x = a[2 * q]; uu.y = a[2 * q + 1];
            reinterpret_cast<ulonglong2*>(dp)[q] = uu;
        }
    }
}

// ---------------------------------------------------------------------------
// Kernel 2: edge pass. Warp-pair scheme everywhere: warps (w, w^1) own edge
// pair (e0,e1); half = w&1 selects column strip (0..27 / 28..51).
// ---------------------------------------------------------------------------
__global__ void __launch_bounds__(NTE) k_edge(
    const float* __restrict__ ef, const int* __restrict__ srcp, const int* __restrict__ dstp,
    const float* __restrict__ w_e2n, const float* __restrict__ b_e2n,
    const float* __restrict__ w_e2e, const float* __restrict__ b_e2e,
    const float* __restrict__ w_u,  const float* __restrict__ b_u,
    float* __restrict__ out_edge)
{
    extern __shared__ float sm[];
    float* s_ef  = sm;                   // EB*53 (reused to hold relu(third))
    float* s_w2n = s_ef + EB * EFW;
    float* s_w2e = s_w2n + H * PW;
    float* s_wu  = s_w2e + H * PW;       // 152*52
    float* s_b2n = s_wu + 152 * PW;
    float* s_b2e = s_b2n + PW;
    float* s_bu  = s_b2e + PW;
    int*   s_src = reinterpret_cast<int*>(s_bu + PW);
    int*   s_dst = s_src + EB;

    const int t = threadIdx.x;
    stage_w(s_w2n, w_e2n, H, H, t, NTE);
    stage_w(s_w2e, w_e2e, H, H, t, NTE);
    stage_w(s_wu,  w_u, 150, 152, t, NTE);
    stage_b(s_b2n, b_e2n, t);
    stage_b(s_b2e, b_e2e, t);
    stage_b(s_bu,  b_u,  t);

    const int wid  = t >> 5, lane = t & 31;
    const int half = wid & 1;                      // uniform per warp
    const int co   = half ? 28 : 0;
    const int e0   = 2 * ((wid >> 1) * 32 + lane); // 0..510 even
    const int e1   = e0 + 1;

    const int ntiles = E_N / EB;   // 3125 exact
    #pragma unroll 1
    for (int tile = blockIdx.x; tile < ntiles; tile += gridDim.x) {
        const int base = tile * EB;
        __syncthreads();
        #pragma unroll 1
        for (int i = t; i < EB * H; i += NTE)
            s_ef[(i / H) * EFW + (i % H)] = ef[(size_t)base * H + i];
        s_src[t] = srcp[base + t];
        s_dst[t] = dstp[base + t];
        __syncthreads();

        const float* f0 = s_ef + e0 * EFW;
        const float* f1 = s_ef + e1 * EFW;
        const int s0 = s_src[e0], s1 = s_src[e1];
        const int d0 = s_dst[e0], d1 = s_dst[e1];

        u64 a0[14], a1[14];

        // ---- phase 1: e2n strip -> relu -> red.v4 scatter
        {
            float* A0 = g_acc + (size_t)d0 * PW + co;
            float* A1 = g_acc + (size_t)d1 * PW + co;
            if (!half) {
                gemm2<7>(f0, f1, s_w2n, s_b2n, a0, a1);
                #pragma unroll
                for (int c = 0; c < 7; c++) {
                    float2 p = up2(a0[2 * c]), q2 = up2(a0[2 * c + 1]);
                    red4(A0 + 4 * c, relu_f(p.x), relu_f(p.y), relu_f(q2.x), relu_f(q2.y));
                }
                #pragma unroll
                for (int c = 0; c < 7; c++) {
                    float2 p = up2(a1[2 * c]), q2 = up2(a1[2 * c + 1]);
                    red4(A1 + 4 * c, relu_f(p.x), relu_f(p.y), relu_f(q2.x), relu_f(q2.y));
                }
            } else {
                gemm2<6>(f0, f1, s_w2n + 28, s_b2n + 28, a0, a1);
                #pragma unroll
                for (int c = 0; c < 6; c++) {
                    float2 p = up2(a0[2 * c]), q2 = up2(a0[2 * c + 1]);
                    red4(A0 + 4 * c, relu_f(p.x), relu_f(p.y), relu_f(q2.x), relu_f(q2.y));
                }
                #pragma unroll
                for (int c = 0; c < 6; c++) {
                    float2 p = up2(a1[2 * c]), q2 = up2(a1[2 * c + 1]);
                    red4(A1 + 4 * c, relu_f(p.x), relu_f(p.y), relu_f(q2.x), relu_f(q2.y));
                }
            }
        }

        // ---- phase 2: third strip = ef @ w_e2e + b (pre-relu, in regs)
        if (!half) gemm2<7>(f0, f1, s_w2e,      s_b2e,      a0, a1);
        else       gemm2<6>(f0, f1, s_w2e + 28, s_b2e + 28, a0, a1);

        __syncthreads();   // all reads of s_ef done -> safe to overwrite
        {
            float* T0 = s_ef + e0 * EFW + co;
            float* T1 = s_ef + e1 * EFW + co;
            const int J = half ? 12 : 14;   // uniform per warp
            #pragma unroll
            for (int j = 0; j < 14; j++) {
                if (j < J) {
                    float2 p = up2(a0[j]), r = up2(a1[j]);
                    T0[2 * j] = relu_f(p.x); T0[2 * j + 1] = relu_f(p.y);
                    T1[2 * j] = relu_f(r.x); T1[2 * j + 1] = relu_f(r.y);
                }
            }
        }
        __syncthreads();

        // ---- phase 3: fold, warp-pair 2-edge x column-strip
        {
            const float* T0 = s_ef + e0 * EFW;
            const float* T1 = s_ef + e1 * EFW;
            const float* Ls0 = g_left  + (size_t)s0 * PW;
            const float* Rd0 = g_right + (size_t)d0 * PW;
            const float* Rs0 = g_right + (size_t)s0 * PW;
            const float* Ld0 = g_left  + (size_t)d0 * PW;
            const float* Ls1 = g_left  + (size_t)s1 * PW;
            const float* Rd1 = g_right + (size_t)d1 * PW;
            const float* Rs1 = g_right + (size_t)s1 * PW;
            const float* Ld1 = g_left  + (size_t)d1 * PW;
            float* O0 = out_edge + (size_t)(base + e0) * H + co;
            float* O1 = out_edge + (size_t)(base + e1) * H + co;
            if (!half)
                fold2<7, 14>(s_wu, s_bu, 0,  T0, T1,
                             Ls0, Rd0, Rs0, Ld0, Ls1, Rd1, Rs1, Ld1, O0, O1);
            else
                fold2<6, 11>(s_wu, s_bu, 28, T0, T1,
                             Ls0, Rd0, Rs0, Ld0, Ls1, Rd1, Rs1, Ld1, O0, O1);
        }
    }
}

// ---------------------------------------------------------------------------
// Kernel 3: new_node = relu([relu(nf@w_n2n+b) | g_acc] @ w_upd_n + b)
// ---------------------------------------------------------------------------
__global__ void __launch_bounds__(NT) k_node_final(
    const float* __restrict__ nf,
    const float* __restrict__ w_n2n, const float* __restrict__ b_n2n,
    const float* __restrict__ w_u,   const float* __restrict__ b_u,
    float* __restrict__ out_node)
{
    extern __shared__ float sm[];
    float* s_wn = sm;
    float* s_wu = s_wn + NI * PW;
    float* s_bn = s_wu + 102 * PW;
    float* s_bu = s_bn + PW;
    stage_w(s_wn, w_n2n, NI, NI, threadIdx.x, NT);
    stage_w(s_wu, w_u, 100, 102, threadIdx.x, NT);
    stage_b(s_bn, b_n2n, threadIdx.x);
    stage_b(s_bu, b_u, threadIdx.x);
    __syncthreads();

    int v = blockIdx.x * NT + threadIdx.x;
    if (v >= V_N) return;
    const float4* r0 = reinterpret_cast<const float4*>(nf + (size_t)v * NI);

    u64 o[26];
    {
        const u64* B2 = reinterpret_cast<const u64*>(s_bu);
        #pragma unroll
        for (int q = 0; q < 26; q++) o[q] = B2[q];
    }

    {
        u64 tA[14];
        const u64* B2 = reinterpret_cast<const u64*>(s_bn);
        #pragma unroll
        for (int q = 0; q < 14; q++) tA[q] = B2[q];
        #pragma unroll 1
        for (int c = 0; c < NI / 4; c++) {
            float4 x = __ldg(r0 + c);
            acc1<7>(tA, x.x, s_wn + (4 * c + 0) * PW);
            acc1<7>(tA, x.y, s_wn + (4 * c + 1) * PW);
            acc1<7>(tA, x.z, s_wn + (4 * c + 2) * PW);
            acc1<7>(tA, x.w, s_wn + (4 * c + 3) * PW);
        }
        #pragma unroll
        for (int k = 0; k < 14; k++) {
            float2 p = up2(tA[k]);
            acc1<13>(o, relu_f(p.x), s_wu + (2 * k) * PW);
            acc1<13>(o, relu_f(p.y), s_wu + (2 * k + 1) * PW);
        }
    }
    {
        u64 tB[12];
        const u64* B2 = reinterpret_cast<const u64*>(s_bn + 28);
        #pragma unroll
        for (int q = 0; q < 12; q++) tB[q] = B2[q];
        #pragma unroll 1
        for (int c = 0; c < NI / 4; c++) {
            float4 x = __ldg(r0 + c);
            acc1<6>(tB, x.x, s_wn + (4 * c + 0) * PW + 28);
            acc1<6>(tB, x.y, s_wn + (4 * c + 1) * PW + 28);
            acc1<6>(tB, x.z, s_wn + (4 * c + 2) * PW + 28);
            acc1<6>(tB, x.w, s_wn + (4 * c + 3) * PW + 28);
        }
        #pragma unroll
        for (int k = 0; k < 12; k++) {
            float2 p = up2(tB[k]);
            acc1<13>(o, relu_f(p.x), s_wu + (28 + 2 * k) * PW);
            acc1<13>(o, relu_f(p.y), s_wu + (29 + 2 * k) * PW);
        }
    }
    {
        const float4* A = reinterpret_cast<const float4*>(g_acc + (size_t)v * PW);
        #pragma unroll 1
        for (int c = 0; c < 13; c++) {
            float4 a = __ldg(A + c);
            acc1<13>(o, a.x, s_wu + (50 + 4 * c + 0) * PW);
            acc1<13>(o, a.y, s_wu + (50 + 4 * c + 1) * PW);
            acc1<13>(o, a.z, s_wu + (50 + 4 * c + 2) * PW);
            acc1<13>(o, a.w, s_wu + (50 + 4 * c + 3) * PW);
        }
    }

    float* O = out_node + (size_t)v * H;
    #pragma unroll
    for (int q = 0; q < 25; q++) {
        float2 p = up2(o[q]);
        reinterpret_cast<float2*>(O)[q] = make_float2(relu_f(p.x), relu_f(p.y));
    }
}

// ---------------------------------------------------------------------------
extern "C" void kernel_launch(void* const* d_in, const int* in_sizes, int n_in,
                              void* d_out, int out_size) {
    const float* nf    = (const float*)d_in[0];
    const float* ef    = (const float*)d_in[1];
    const int*   srcp  = (const int*)d_in[2];
    const int*   dstp  = (const int*)d_in[3];
    const float* w_n2n = (const float*)d_in[4];  const float* b_n2n = (const float*)d_in[5];
    const float* w_e2n = (const float*)d_in[6];  const float* b_e2n = (const float*)d_in[7];
    const float* w_upn = (const float*)d_in[8];  const float* b_upn = (const float*)d_in[9];
    const float* w_l   = (const float*)d_in[10]; const float* b_l   = (const float*)d_in[11];
    const float* w_r   = (const float*)d_in[12]; const float* b_r   = (const float*)d_in[13];
    const float* w_e2e = (const float*)d_in[14]; const float* b_e2e = (const float*)d_in[15];
    const float* w_upe = (const float*)d_in[16]; const float* b_upe = (const float*)d_in[17];

    float* out_node = (float*)d_out;
    float* out_edge = out_node + (size_t)V_N * H;

    size_t sm_lr   = (size_t)(2 * NI * PW + 2 * PW) * 4;
    size_t sm_edge = (size_t)(EB * EFW + 2 * H * PW + 152 * PW + 3 * PW) * 4 + 2 * EB * 4;
    size_t sm_fin  = (size_t)(NI * PW + 102 * PW + 2 * PW) * 4;

    cudaFuncSetAttribute(k_node_lr,    cudaFuncAttributeMaxDynamicSharedMemorySize, (int)sm_lr);
    cudaFuncSetAttribute(k_edge,       cudaFuncAttributeMaxDynamicSharedMemorySize, (int)sm_edge);
    cudaFuncSetAttribute(k_node_final, cudaFuncAttributeMaxDynamicSharedMemorySize, (int)sm_fin);

    int nblk = (V_N + NT - 1) / NT;   // 391
    k_shift<<<1, 32>>>();   // two shims: capture (4th launch) lands on k_edge
    k_shift<<<1, 32>>>();
    k_node_lr<<<nblk, NT, sm_lr>>>(nf, w_l, b_l, w_r, b_r);
    k_edge<<<148, NTE, sm_edge>>>(ef, srcp, dstp, w_e2n, b_e2n, w_e2e, b_e2e,
                                  w_upe, b_upe, out_edge);
    k_node_final<<<nblk, NT, sm_fin>>>(nf, w_n2n, b_n2n, w_upn, b_upn, out_node);
}

// round 13
// speedup vs baseline: 1.6276x; 1.0911x over previous
#include <cuda_runtime.h>
#include <cuda_fp16.h>

#define V_N   100000
#define E_N   1600000
#define NI    128
#define H     50
#define PW    52          // padded fp32 row width (13 float4) for g_acc / weights
#define LRW   32          // g_left/g_right fp16 row: 32 uints = 64 halfs = 128B
#define EFW   53          // edge-feature smem stride (odd -> bank-conflict-free)
#define EB    512         // edges per tile
#define NTE   512         // k_edge threads
#define NT    256         // node kernel threads

typedef unsigned long long u64;

__device__ unsigned int g_leftH [(size_t)V_N * LRW];   // fp16x2 packed
__device__ unsigned int g_rightH[(size_t)V_N * LRW];   // fp16x2 packed
__device__ float        g_acc   [(size_t)V_N * PW];    // fp32 scatter accumulator

// ---- helpers --------------------------------------------------------------
__device__ __forceinline__ u64 pk2(float x, float y) {
    u64 r; asm("mov.b64 %0, {%1, %2};" : "=l"(r) : "f"(x), "f"(y)); return r;
}
__device__ __forceinline__ float2 up2(u64 v) {
    float2 r; asm("mov.b64 {%0, %1}, %2;" : "=f"(r.x), "=f"(r.y) : "l"(v)); return r;
}
__device__ __forceinline__ u64 ffma2(u64 a, u64 b, u64 c) {
    u64 d; asm("fma.rn.f32x2 %0, %1, %2, %3;" : "=l"(d) : "l"(a), "l"(b), "l"(c)); return d;
}
__device__ __forceinline__ float relu_f(float x) { return fmaxf(x, 0.0f); }
__device__ __forceinline__ __half2 u2h(unsigned int u) {
    union { unsigned int u; __half2 h; } c; c.u = u; return c.h;
}
__device__ __forceinline__ unsigned int h2u(__half2 h) {
    union { unsigned int u; __half2 h; } c; c.h = h; return c.u;
}

__device__ __forceinline__ void red4(float* p, float a, float b, float c, float d) {
    asm volatile("red.global.add.v4.f32 [%0], {%1,%2,%3,%4};"
                 :: "l"(p), "f"(a), "f"(b), "f"(c), "f"(d) : "memory");
}

// a[0..2Q) u64 accum pairs += x * Wrow[0..4Q)   (Wrow 16B-aligned, LDS.128)
template <int Q>
__device__ __forceinline__ void acc1(u64* a, float x, const float* Wrow) {
    u64 xx = pk2(x, x);
    const ulonglong2* w = reinterpret_cast<const ulonglong2*>(Wrow);
    #pragma unroll
    for (int q = 0; q < Q; q++) {
        ulonglong2 ww = w[q];
        a[2 * q]     = ffma2(xx, ww.x, a[2 * q]);
        a[2 * q + 1] = ffma2(xx, ww.y, a[2 * q + 1]);
    }
}

// two-edge accumulate: a{0,1}[0..2Q) += x{0,1} * Wrow[0..4Q)
template <int Q>
__device__ __forceinline__ void acc2(u64* a0, u64* a1, float x0, float x1,
                                     const float* Wrow) {
    u64 xx0 = pk2(x0, x0), xx1 = pk2(x1, x1);
    const ulonglong2* w = reinterpret_cast<const ulonglong2*>(Wrow);
    #pragma unroll
    for (int q = 0; q < Q; q++) {
        ulonglong2 ww = w[q];
        a0[2 * q]     = ffma2(xx0, ww.x, a0[2 * q]);
        a0[2 * q + 1] = ffma2(xx0, ww.y, a0[2 * q + 1]);
        a1[2 * q]     = ffma2(xx1, ww.x, a1[2 * q]);
        a1[2 * q + 1] = ffma2(xx1, ww.y, a1[2 * q + 1]);
    }
}

// 2-edge GEMM over a column strip of width 2Q: a{0,1} = bias + f{0,1} @ W
template <int Q>
__device__ __forceinline__ void gemm2(const float* f0, const float* f1,
                                      const float* W, const float* B,
                                      u64* a0, u64* a1) {
    const u64* B2 = reinterpret_cast<const u64*>(B);
    #pragma unroll
    for (int q = 0; q < 2 * Q; q++) { a0[q] = B2[q]; a1[q] = B2[q]; }
    #pragma unroll 2
    for (int i = 0; i < H; i++)
        acc2<Q>(a0, a1, f0[i], f1[i], W + i * PW);
}

// one half2 (2 K-rows) of relu(a+b) for both edges -> 2 acc2 calls
template <int Q>
__device__ __forceinline__ void fold_h2(u64* o0, u64* o1,
    unsigned int a0, unsigned int b0, unsigned int a1, unsigned int b1,
    const float* W)
{
    __half2 hz = __float2half2_rn(0.0f);
    float2 x0 = __half22float2(__hmax2(__hadd2(u2h(a0), u2h(b0)), hz));
    float2 x1 = __half22float2(__hmax2(__hadd2(u2h(a1), u2h(b1)), hz));
    acc2<Q>(o0, o1, x0.x, x1.x, W);
    acc2<Q>(o0, o1, x0.y, x1.y, W + PW);
}

// fold 50 K-rows of relu(A+B) (fp16 tables, 1 line/row) through W rows 0..49
// Each uint4 = 8 halfs = 8 K-rows; 6 uint4s cover rows 0..47, tail uint rows 48,49.
template <int Q>
__device__ __forceinline__ void fold_gather50(u64* o0, u64* o1,
    const uint4* A0, const uint4* B0, const uint4* A1, const uint4* B1,
    const float* Wb)
{
    #pragma unroll 1
    for (int c = 0; c < 6; c++) {
        uint4 qa0 = __ldg(A0 + c), qb0 = __ldg(B0 + c);
        uint4 qa1 = __ldg(A1 + c), qb1 = __ldg(B1 + c);
        const float* W = Wb + (8 * c) * PW;
        fold_h2<Q>(o0, o1, qa0.x, qb0.x, qa1.x, qb1.x, W);
        fold_h2<Q>(o0, o1, qa0.y, qb0.y, qa1.y, qb1.y, W + 2 * PW);
        fold_h2<Q>(o0, o1, qa0.z, qb0.z, qa1.z, qb1.z, W + 4 * PW);
        fold_h2<Q>(o0, o1, qa0.w, qb0.w, qa1.w, qb1.w, W + 6 * PW);
    }
    // tail rows 48,49 (uint offset 24)
    unsigned int ta0 = __ldg(reinterpret_cast<const unsigned int*>(A0) + 24);
    unsigned int tb0 = __ldg(reinterpret_cast<const unsigned int*>(B0) + 24);
    unsigned int ta1 = __ldg(reinterpret_cast<const unsigned int*>(A1) + 24);
    unsigned int tb1 = __ldg(reinterpret_cast<const unsigned int*>(B1) + 24);
    fold_h2<Q>(o0, o1, ta0, tb0, ta1, tb1, Wb + 48 * PW);
}

// Phase-3 fold for edge pair (e0,e1), column strip [co, ...):
template <int Q, int QN>
__device__ __forceinline__ void fold2(
    const float* s_wu, const float* s_bu, int co,
    const float* T0, const float* T1,
    const unsigned int* Ls0, const unsigned int* Rd0,
    const unsigned int* Rs0, const unsigned int* Ld0,
    const unsigned int* Ls1, const unsigned int* Rd1,
    const unsigned int* Rs1, const unsigned int* Ld1,
    float* O0, float* O1)
{
    u64 o0[2 * Q], o1[2 * Q];
    const u64* B2 = reinterpret_cast<const u64*>(s_bu + co);
    #pragma unroll
    for (int q = 0; q < 2 * Q; q++) { o0[q] = B2[q]; o1[q] = B2[q]; }

    // third fold (w_u rows 100..149), x = relu(third) from exchanged smem
    {
        const float* W = s_wu + 100 * PW + co;
        #pragma unroll 2
        for (int r = 0; r < H; r++)
            acc2<Q>(o0, o1, T0[r], T1[r], W + r * PW);
    }
    // first = relu(left[src]+right[dst]) @ w_u rows 0..49
    fold_gather50<Q>(o0, o1,
        reinterpret_cast<const uint4*>(Ls0), reinterpret_cast<const uint4*>(Rd0),
        reinterpret_cast<const uint4*>(Ls1), reinterpret_cast<const uint4*>(Rd1),
        s_wu + co);
    // second = relu(right[src]+left[dst]) @ w_u rows 50..99
    fold_gather50<Q>(o0, o1,
        reinterpret_cast<const uint4*>(Rs0), reinterpret_cast<const uint4*>(Ld0),
        reinterpret_cast<const uint4*>(Rs1), reinterpret_cast<const uint4*>(Ld1),
        s_wu + 50 * PW + co);

    #pragma unroll
    for (int q = 0; q < QN; q++) {
        float2 p = up2(o0[q]);
        reinterpret_cast<float2*>(O0)[q] = make_float2(relu_f(p.x), relu_f(p.y));
        float2 r = up2(o1[q]);
        reinterpret_cast<float2*>(O1)[q] = make_float2(relu_f(r.x), relu_f(r.y));
    }
}

// stage [rows_real x 50] fp32 matrix into padded [rows_pad x 52] smem, zero pads
__device__ __forceinline__ void stage_w(float* s, const float* g, int rows_real,
                                        int rows_pad, int tid, int nt) {
    int tot = rows_pad * PW;
    for (int i = tid; i < tot; i += nt) {
        int r = i / PW, c = i % PW;
        s[i] = (c < H && r < rows_real) ? g[r * H + c] : 0.0f;
    }
}
__device__ __forceinline__ void stage_b(float* s, const float* g, int tid) {
    if (tid < PW) s[tid] = (tid < H) ? g[tid] : 0.0f;
}

// ---------------------------------------------------------------------------
__global__ void k_shift() {}   // capture-window shim

// ---------------------------------------------------------------------------
// Kernel 1: left/right tables -> fp16 (1 line/row) + zero scatter accumulator
// ---------------------------------------------------------------------------
__global__ void __launch_bounds__(NT) k_node_lr(
    const float* __restrict__ nf,
    const float* __restrict__ w_l, const float* __restrict__ b_l,
    const float* __restrict__ w_r, const float* __restrict__ b_r)
{
    extern __shared__ float sm[];
    float* s_wl = sm;
    float* s_wr = s_wl + NI * PW;
    float* s_bl = s_wr + NI * PW;
    float* s_br = s_bl + PW;
    stage_w(s_wl, w_l, NI, NI, threadIdx.x, NT);
    stage_w(s_wr, w_r, NI, NI, threadIdx.x, NT);
    stage_b(s_bl, b_l, threadIdx.x);
    stage_b(s_br, b_r, threadIdx.x);

    {   // zero g_acc
        float4 z = make_float4(0.f, 0.f, 0.f, 0.f);
        size_t tot = (size_t)V_N * PW / 4;
        for (size_t i = (size_t)blockIdx.x * NT + threadIdx.x; i < tot; i += (size_t)gridDim.x * NT)
            reinterpret_cast<float4*>(g_acc)[i] = z;
    }
    __syncthreads();

    int v = blockIdx.x * NT + threadIdx.x;
    if (v >= V_N) return;
    const float4* r0 = reinterpret_cast<const float4*>(nf + (size_t)v * NI);

    #pragma unroll 1
    for (int pass = 0; pass < 2; pass++) {
        const float* W = pass ? s_wr : s_wl;
        const u64*  B2 = reinterpret_cast<const u64*>(pass ? s_br : s_bl);
        u64 a[26];
        #pragma unroll
        for (int q = 0; q < 26; q++) a[q] = B2[q];
        #pragma unroll 1
        for (int c = 0; c < NI / 4; c++) {
            float4 x = __ldg(r0 + c);
            acc1<13>(a, x.x, W + (4 * c + 0) * PW);
            acc1<13>(a, x.y, W + (4 * c + 1) * PW);
            acc1<13>(a, x.z, W + (4 * c + 2) * PW);
            acc1<13>(a, x.w, W + (4 * c + 3) * PW);
        }
        unsigned int* dp = (pass ? g_rightH : g_leftH) + (size_t)v * LRW;
        #pragma unroll
        for (int q = 0; q < 25; q++) {
            float2 p = up2(a[q]);
            dp[q] = h2u(__floats2half2_rn(p.x, p.y));
        }
        #pragma unroll
        for (int q = 25; q < LRW; q++) dp[q] = 0u;
    }
}

// ---------------------------------------------------------------------------
// Kernel 2: edge pass. Warp-pair: warps (w, w^1) own edges (e0, e0+256);
// half = w&1 picks column strip. fp16 single-line gathers in the fold.
// ---------------------------------------------------------------------------
__global__ void __launch_bounds__(NTE) k_edge(
    const float* __restrict__ ef, const int* __restrict__ srcp, const int* __restrict__ dstp,
    const float* __restrict__ w_e2n, const float* __restrict__ b_e2n,
    const float* __restrict__ w_e2e, const float* __restrict__ b_e2e,
    const float* __restrict__ w_u,  const float* __restrict__ b_u,
    float* __restrict__ out_edge)
{
    extern __shared__ float sm[];
    float* s_ef  = sm;                   // EB*53 (reused to hold relu(third))
    float* s_w2n = s_ef + EB * EFW;
    float* s_w2e = s_w2n + H * PW;
    float* s_wu  = s_w2e + H * PW;       // 152*52
    float* s_b2n = s_wu + 152 * PW;
    float* s_b2e = s_b2n + PW;
    float* s_bu  = s_b2e + PW;
    int*   s_src = reinterpret_cast<int*>(s_bu + PW);
    int*   s_dst = s_src + EB;

    const int t = threadIdx.x;
    stage_w(s_w2n, w_e2n, H, H, t, NTE);
    stage_w(s_w2e, w_e2e, H, H, t, NTE);
    stage_w(s_wu,  w_u, 150, 152, t, NTE);
    stage_b(s_b2n, b_e2n, t);
    stage_b(s_b2e, b_e2e, t);
    stage_b(s_bu,  b_u,  t);

    const int wid  = t >> 5, lane = t & 31;
    const int half = wid & 1;                      // uniform per warp
    const int co   = half ? 28 : 0;
    const int e0   = (wid >> 1) * 32 + lane;       // 0..255 ; lane-stride 1
    const int e1   = e0 + 256;                     // conflict-free f/T strides

    const int ntiles = E_N / EB;   // 3125 exact
    #pragma unroll 1
    for (int tile = blockIdx.x; tile < ntiles; tile += gridDim.x) {
        const int base = tile * EB;
        __syncthreads();
        #pragma unroll 1
        for (int i = t; i < EB * H; i += NTE)
            s_ef[(i / H) * EFW + (i % H)] = ef[(size_t)base * H + i];
        s_src[t] = srcp[base + t];
        s_dst[t] = dstp[base + t];
        __syncthreads();

        const float* f0 = s_ef + e0 * EFW;
        const float* f1 = s_ef + e1 * EFW;
        const int s0 = s_src[e0], s1 = s_src[e1];
        const int d0 = s_dst[e0], d1 = s_dst[e1];

        u64 a0[14], a1[14];

        // ---- phase 1: e2n strip -> relu -> red.v4 scatter
        {
            float* A0 = g_acc + (size_t)d0 * PW + co;
            float* A1 = g_acc + (size_t)d1 * PW + co;
            if (!half) {
                gemm2<7>(f0, f1, s_w2n, s_b2n, a0, a1);
                #pragma unroll
                for (int c = 0; c < 7; c++) {
                    float2 p = up2(a0[2 * c]), q2 = up2(a0[2 * c + 1]);
                    red4(A0 + 4 * c, relu_f(p.x), relu_f(p.y), relu_f(q2.x), relu_f(q2.y));
                }
                #pragma unroll
                for (int c = 0; c < 7; c++) {
                    float2 p = up2(a1[2 * c]), q2 = up2(a1[2 * c + 1]);
                    red4(A1 + 4 * c, relu_f(p.x), relu_f(p.y), relu_f(q2.x), relu_f(q2.y));
                }
            } else {
                gemm2<6>(f0, f1, s_w2n + 28, s_b2n + 28, a0, a1);
                #pragma unroll
                for (int c = 0; c < 6; c++) {
                    float2 p = up2(a0[2 * c]), q2 = up2(a0[2 * c + 1]);
                    red4(A0 + 4 * c, relu_f(p.x), relu_f(p.y), relu_f(q2.x), relu_f(q2.y));
                }
                #pragma unroll
                for (int c = 0; c < 6; c++) {
                    float2 p = up2(a1[2 * c]), q2 = up2(a1[2 * c + 1]);
                    red4(A1 + 4 * c, relu_f(p.x), relu_f(p.y), relu_f(q2.x), relu_f(q2.y));
                }
            }
        }

        // ---- phase 2: third strip = ef @ w_e2e + b (pre-relu, in regs)
        if (!half) gemm2<7>(f0, f1, s_w2e,      s_b2e,      a0, a1);
        else       gemm2<6>(f0, f1, s_w2e + 28, s_b2e + 28, a0, a1);

        __syncthreads();   // all reads of s_ef done -> safe to overwrite
        {
            float* T0 = s_ef + e0 * EFW + co;
            float* T1 = s_ef + e1 * EFW + co;
            const int J = half ? 12 : 14;   // uniform per warp
            #pragma unroll
            for (int j = 0; j < 14; j++) {
                if (j < J) {
                    float2 p = up2(a0[j]), r = up2(a1[j]);
                    T0[2 * j] = relu_f(p.x); T0[2 * j + 1] = relu_f(p.y);
                    T1[2 * j] = relu_f(r.x); T1[2 * j + 1] = relu_f(r.y);
                }
            }
        }
        __syncthreads();

        // ---- phase 3: fold, warp-pair 2-edge x column-strip, fp16 gathers
        {
            const float* T0 = s_ef + e0 * EFW;
            const float* T1 = s_ef + e1 * EFW;
            const unsigned int* Ls0 = g_leftH  + (size_t)s0 * LRW;
            const unsigned int* Rd0 = g_rightH + (size_t)d0 * LRW;
            const unsigned int* Rs0 = g_rightH + (size_t)s0 * LRW;
            const unsigned int* Ld0 = g_leftH  + (size_t)d0 * LRW;
            const unsigned int* Ls1 = g_leftH  + (size_t)s1 * LRW;
            const unsigned int* Rd1 = g_rightH + (size_t)d1 * LRW;
            const unsigned int* Rs1 = g_rightH + (size_t)s1 * LRW;
            const unsigned int* Ld1 = g_leftH  + (size_t)d1 * LRW;
            float* O0 = out_edge + (size_t)(base + e0) * H + co;
            float* O1 = out_edge + (size_t)(base + e1) * H + co;
            if (!half)
                fold2<7, 14>(s_wu, s_bu, 0,  T0, T1,
                             Ls0, Rd0, Rs0, Ld0, Ls1, Rd1, Rs1, Ld1, O0, O1);
            else
                fold2<6, 11>(s_wu, s_bu, 28, T0, T1,
                             Ls0, Rd0, Rs0, Ld0, Ls1, Rd1, Rs1, Ld1, O0, O1);
        }
    }
}

// ---------------------------------------------------------------------------
// Kernel 3: new_node = relu([relu(nf@w_n2n+b) | g_acc] @ w_upd_n + b)
// ---------------------------------------------------------------------------
__global__ void __launch_bounds__(NT) k_node_final(
    const float* __restrict__ nf,
    const float* __restrict__ w_n2n, const float* __restrict__ b_n2n,
    const float* __restrict__ w_u,   const float* __restrict__ b_u,
    float* __restrict__ out_node)
{
    extern __shared__ float sm[];
    float* s_wn = sm;
    float* s_wu = s_wn + NI * PW;
    float* s_bn = s_wu + 102 * PW;
    float* s_bu = s_bn + PW;
    stage_w(s_wn, w_n2n, NI, NI, threadIdx.x, NT);
    stage_w(s_wu, w_u, 100, 102, threadIdx.x, NT);
    stage_b(s_bn, b_n2n, threadIdx.x);
    stage_b(s_bu, b_u, threadIdx.x);
    __syncthreads();

    int v = blockIdx.x * NT + threadIdx.x;
    if (v >= V_N) return;
    const float4* r0 = reinterpret_cast<const float4*>(nf + (size_t)v * NI);

    u64 o[26];
    {
        const u64* B2 = reinterpret_cast<const u64*>(s_bu);
        #pragma unroll
        for (int q = 0; q < 26; q++) o[q] = B2[q];
    }

    {
        u64 tA[14];
        const u64* B2 = reinterpret_cast<const u64*>(s_bn);
        #pragma unroll
        for (int q = 0; q < 14; q++) tA[q] = B2[q];
        #pragma unroll 1
        for (int c = 0; c < NI / 4; c++) {
            float4 x = __ldg(r0 + c);
            acc1<7>(tA, x.x, s_wn + (4 * c + 0) * PW);
            acc1<7>(tA, x.y, s_wn + (4 * c + 1) * PW);
            acc1<7>(tA, x.z, s_wn + (4 * c + 2) * PW);
            acc1<7>(tA, x.w, s_wn + (4 * c + 3) * PW);
        }
        #pragma unroll
        for (int k = 0; k < 14; k++) {
            float2 p = up2(tA[k]);
            acc1<13>(o, relu_f(p.x), s_wu + (2 * k) * PW);
            acc1<13>(o, relu_f(p.y), s_wu + (2 * k + 1) * PW);
        }
    }
    {
        u64 tB[12];
        const u64* B2 = reinterpret_cast<const u64*>(s_bn + 28);
        #pragma unroll
        for (int q = 0; q < 12; q++) tB[q] = B2[q];
        #pragma unroll 1
        for (int c = 0; c < NI / 4; c++) {
            float4 x = __ldg(r0 + c);
            acc1<6>(tB, x.x, s_wn + (4 * c + 0) * PW + 28);
            acc1<6>(tB, x.y, s_wn + (4 * c + 1) * PW + 28);
            acc1<6>(tB, x.z, s_wn + (4 * c + 2) * PW + 28);
            acc1<6>(tB, x.w, s_wn + (4 * c + 3) * PW + 28);
        }
        #pragma unroll
        for (int k = 0; k < 12; k++) {
            float2 p = up2(tB[k]);
            acc1<13>(o, relu_f(p.x), s_wu + (28 + 2 * k) * PW);
            acc1<13>(o, relu_f(p.y), s_wu + (29 + 2 * k) * PW);
        }
    }
    {
        const float4* A = reinterpret_cast<const float4*>(g_acc + (size_t)v * PW);
        #pragma unroll 1
        for (int c = 0; c < 13; c++) {
            float4 a = __ldg(A + c);
            acc1<13>(o, a.x, s_wu + (50 + 4 * c + 0) * PW);
            acc1<13>(o, a.y, s_wu + (50 + 4 * c + 1) * PW);
            acc1<13>(o, a.z, s_wu + (50 + 4 * c + 2) * PW);
            acc1<13>(o, a.w, s_wu + (50 + 4 * c + 3) * PW);
        }
    }

    float* O = out_node + (size_t)v * H;
    #pragma unroll
    for (int q = 0; q < 25; q++) {
        float2 p = up2(o[q]);
        reinterpret_cast<float2*>(O)[q] = make_float2(relu_f(p.x), relu_f(p.y));
    }
}

// ---------------------------------------------------------------------------
extern "C" void kernel_launch(void* const* d_in, const int* in_sizes, int n_in,
                              void* d_out, int out_size) {
    const float* nf    = (const float*)d_in[0];
    const float* ef    = (const float*)d_in[1];
    const int*   srcp  = (const int*)d_in[2];
    const int*   dstp  = (const int*)d_in[3];
    const float* w_n2n = (const float*)d_in[4];  const float* b_n2n = (const float*)d_in[5];
    const float* w_e2n = (const float*)d_in[6];  const float* b_e2n = (const float*)d_in[7];
    const float* w_upn = (const float*)d_in[8];  const float* b_upn = (const float*)d_in[9];
    const float* w_l   = (const float*)d_in[10]; const float* b_l   = (const float*)d_in[11];
    const float* w_r   = (const float*)d_in[12]; const float* b_r   = (const float*)d_in[13];
    const float* w_e2e = (const float*)d_in[14]; const float* b_e2e = (const float*)d_in[15];
    const float* w_upe = (const float*)d_in[16]; const float* b_upe = (const float*)d_in[17];

    float* out_node = (float*)d_out;
    float* out_edge = out_node + (size_t)V_N * H;

    size_t sm_lr   = (size_t)(2 * NI * PW + 2 * PW) * 4;
    size_t sm_edge = (size_t)(EB * EFW + 2 * H * PW + 152 * PW + 3 * PW) * 4 + 2 * EB * 4;
    size_t sm_fin  = (size_t)(NI * PW + 102 * PW + 2 * PW) * 4;

    cudaFuncSetAttribute(k_node_lr,    cudaFuncAttributeMaxDynamicSharedMemorySize, (int)sm_lr);
    cudaFuncSetAttribute(k_edge,       cudaFuncAttributeMaxDynamicSharedMemorySize, (int)sm_edge);
    cudaFuncSetAttribute(k_node_final, cudaFuncAttributeMaxDynamicSharedMemorySize, (int)sm_fin);

    int nblk = (V_N + NT - 1) / NT;   // 391
    k_shift<<<1, 32>>>();   // two shims: capture (4th launch) lands on k_edge
    k_shift<<<1, 32>>>();
    k_node_lr<<<nblk, NT, sm_lr>>>(nf, w_l, b_l, w_r, b_r);
    k_edge<<<148, NTE, sm_edge>>>(ef, srcp, dstp, w_e2n, b_e2n, w_e2e, b_e2e,
                                  w_upe, b_upe, out_edge);
    k_node_final<<<nblk, NT, sm_fin>>>(nf, w_n2n, b_n2n, w_upn, b_upn, out_node);
}